// round 7
// baseline (speedup 1.0000x reference)
#include <cuda_runtime.h>

// ---------------------------------------------------------------------------
// MaskedBalancedBCELoss — 2-kernel pipeline.
//  K1 (one 157 MB streaming read): counts pos/valid in regs; u8-packed 16-bin
//     histogram of p over CANDIDATES only (negatives with p>=0.5, <=60
//     elements/thread so no overflow); ballot-compacts tagged candidates
//     (negatives as +p, positives as -p) into per-block scratch regions.
//  K2 : derives threshold bin T1 from the histogram; one pass over scratch
//      accumulating log-sums via mantissa-product + exponent counter
//      (positives -> pos_sum, negative bins > T1 -> above_sum, bin == T1 ->
//      exact log + 64-sub-bin count/sum hist). Cold fallback (T1 below bin 16
//      or no scratch): full re-read with 1024 fine bins. The LAST block
//      (fence + atomic counter) finalizes: preloads histograms to SMEM in
//      parallel, resolves the crossing sub-bin (mean interpolation), writes
//      the scalar, and resets all globals (CUDA-graph-replay safe).
// ---------------------------------------------------------------------------

#define NB1 16             // bins 16..31 of (int)(p*32)
#define NB2 64
#define NFB 1024           // fine bins over [0,0.5) for the cold fallback
#define BLK 256
#define GRID_CAP 888
#define SCR_SZ (16u << 20) // 16M floats = 64 MB

__device__ __align__(16) float g_scr[SCR_SZ];
__device__ unsigned int g_cnt_blk[GRID_CAP];
__device__ unsigned int g_h1[NB1];
__device__ unsigned int g_h2c[NB2];
__device__ float        g_h2s[NB2];
__device__ unsigned int g_fc[NFB];
__device__ float        g_fs[NFB];
__device__ unsigned int g_pos_cnt;
__device__ unsigned int g_neg_cnt;
__device__ double       g_pos_sum;
__device__ double       g_above_sum;
__device__ unsigned int g_done;

// Cephes-style natural log, pure FMA/ALU (no MUFU). ~1-2 ulp on normals.
__device__ __forceinline__ float fast_log(float x) {
    int   i  = __float_as_int(x);
    int   e  = ((i >> 23) & 0xFF) - 127;
    float m  = __int_as_float((i & 0x007FFFFF) | 0x3F800000);
    if (m > 1.41421356f) { m *= 0.5f; e += 1; }
    float t  = m - 1.0f;
    float z  = t * t;
    float P  = 7.0376836292e-2f;
    P = P * t - 1.1514610310e-1f;
    P = P * t + 1.1676998740e-1f;
    P = P * t - 1.2420140846e-1f;
    P = P * t + 1.4249322787e-1f;
    P = P * t - 1.6668057665e-1f;
    P = P * t + 2.0000714765e-1f;
    P = P * t - 2.4999993993e-1f;
    P = P * t + 3.3333331174e-1f;
    float fe = (float)e;
    float y  = t * z * P;
    y += fe * -2.12194440e-4f;
    y -= 0.5f * z;
    float r  = t + y;
    r += fe * 0.693359375f;
    return r;
}
__device__ __forceinline__ float pos_loss_f(float p) { return fminf(-fast_log(p), 100.0f); }
__device__ __forceinline__ float neg_loss_f(float p) { return fminf(-fast_log(1.0f - p), 100.0f); }

// log-sum accumulator: product of mantissas kept in [1,2), exponent in int.
__device__ __forceinline__ void acc_log(float x, float& m, int& e) {
    m *= x;
    int i = __float_as_int(m);
    e += ((i >> 23) & 0xFF) - 127;
    m = __int_as_float((i & 0x807FFFFFu) | 0x3F800000u);
}
__device__ __forceinline__ float finish_log(float m, int e) {
    return -(fast_log(m) + (float)e * 0.69314718056f);
}

// Threshold bin. 1000 if k==0; -1 if below bin 16 (cold); else T1 in [16,31].
__device__ __forceinline__ int find_T1(const unsigned* h1, unsigned pos,
                                       long long negtot, long long& k_out) {
    long long k3p = 3LL * (long long)pos;
    long long k = (pos == 0u) ? 0LL : (negtot < k3p ? negtot : k3p);
    k_out = k;
    if (k == 0) return 1000;
    long long c = 0;
    for (int i = NB1 - 1; i >= 0; i--) {
        c += (long long)h1[i];
        if (c >= k) return i + 16;
    }
    return -1;
}

// ---------------------------------------------------------------------------
// K1: stream, classify, candidate histogram, compact.
// ---------------------------------------------------------------------------
__global__ void __launch_bounds__(BLK, 6) k1_scan(
    const float4* __restrict__ pred4, const float4* __restrict__ gt4,
    const float4* __restrict__ mask4,
    const float* __restrict__ pred, const float* __restrict__ gt,
    const float* __restrict__ mask, int n, int cap, int use_scr)
{
    __shared__ unsigned int sh[4 * BLK];   // u8-packed 16-bin candidate hist
    __shared__ unsigned int s_binsum[NB1];
    __shared__ unsigned int s_cnt;
    __shared__ unsigned int w_pc[BLK / 32], w_vc[BLK / 32];

    const int tid  = threadIdx.x;
    const int lane = tid & 31;
    const unsigned lt = (1u << lane) - 1u;

#pragma unroll
    for (int w = 0; w < 4; w++) sh[w * BLK + tid] = 0u;
    if (tid < NB1) s_binsum[tid] = 0u;
    if (tid == 0) s_cnt = 0u;
    __syncthreads();

    unsigned int posc = 0, valc = 0;
    const int n4   = n >> 2;
    const int step = gridDim.x * BLK;
    const long long rb = (long long)blockIdx.x * (long long)cap;

    auto procE = [&](float p, float g, float mm, bool in, float& v) -> bool {
        bool valid = in && (mm > 0.5f);
        bool ispos = valid && (g > 0.5f);
        valc += valid ? 1u : 0u;
        posc += ispos ? 1u : 0u;
        v = ispos ? -p : p;
        bool cand = valid && !(g > 0.5f) && (p >= 0.5f);
        if (cand) {
            int idx = min((int)(p * 32.0f), 31) - 16;   // 0..15
            sh[(idx >> 2) * BLK + tid] += 1u << ((idx & 3) << 3);
        }
        return ispos || cand;
    };

    int ibase = blockIdx.x * BLK;
    while (ibase + step + BLK <= n4) {
        int i0 = ibase + tid, i1 = i0 + step;
        float4 pa = __ldcs(&pred4[i0]), ga = __ldcs(&gt4[i0]), ma = __ldcs(&mask4[i0]);
        float4 pb = __ldcs(&pred4[i1]), gb = __ldcs(&gt4[i1]), mb = __ldcs(&mask4[i1]);
        float v0, v1, v2, v3, v4, v5, v6, v7;
        bool c0 = procE(pa.x, ga.x, ma.x, true, v0);
        bool c1 = procE(pa.y, ga.y, ma.y, true, v1);
        bool c2 = procE(pa.z, ga.z, ma.z, true, v2);
        bool c3 = procE(pa.w, ga.w, ma.w, true, v3);
        bool c4 = procE(pb.x, gb.x, mb.x, true, v4);
        bool c5 = procE(pb.y, gb.y, mb.y, true, v5);
        bool c6 = procE(pb.z, gb.z, mb.z, true, v6);
        bool c7 = procE(pb.w, gb.w, mb.w, true, v7);
        if (use_scr) {
            unsigned m0 = __ballot_sync(0xffffffffu, c0);
            unsigned m1 = __ballot_sync(0xffffffffu, c1);
            unsigned m2 = __ballot_sync(0xffffffffu, c2);
            unsigned m3 = __ballot_sync(0xffffffffu, c3);
            unsigned m4 = __ballot_sync(0xffffffffu, c4);
            unsigned m5 = __ballot_sync(0xffffffffu, c5);
            unsigned m6 = __ballot_sync(0xffffffffu, c6);
            unsigned m7 = __ballot_sync(0xffffffffu, c7);
            unsigned tot = __popc(m0) + __popc(m1) + __popc(m2) + __popc(m3)
                         + __popc(m4) + __popc(m5) + __popc(m6) + __popc(m7);
            unsigned base = 0;
            if (lane == 0 && tot) base = atomicAdd(&s_cnt, tot);
            base = __shfl_sync(0xffffffffu, base, 0);
            unsigned s = base;
            if (c0) g_scr[rb + s + __popc(m0 & lt)] = v0; s += __popc(m0);
            if (c1) g_scr[rb + s + __popc(m1 & lt)] = v1; s += __popc(m1);
            if (c2) g_scr[rb + s + __popc(m2 & lt)] = v2; s += __popc(m2);
            if (c3) g_scr[rb + s + __popc(m3 & lt)] = v3; s += __popc(m3);
            if (c4) g_scr[rb + s + __popc(m4 & lt)] = v4; s += __popc(m4);
            if (c5) g_scr[rb + s + __popc(m5 & lt)] = v5; s += __popc(m5);
            if (c6) g_scr[rb + s + __popc(m6 & lt)] = v6; s += __popc(m6);
            if (c7) g_scr[rb + s + __popc(m7 & lt)] = v7;
        }
        ibase += 2 * step;
    }
    for (; ibase < n4; ibase += step) {   // block-uniform trips
        int i = ibase + tid;
        bool in = i < n4;
        float4 pa = in ? __ldcs(&pred4[i]) : make_float4(0.f, 0.f, 0.f, 0.f);
        float4 ga = in ? __ldcs(&gt4[i])   : make_float4(1.f, 1.f, 1.f, 1.f);
        float4 ma = in ? __ldcs(&mask4[i]) : make_float4(0.f, 0.f, 0.f, 0.f);
        float v0, v1, v2, v3;
        bool c0 = procE(pa.x, ga.x, ma.x, in, v0);
        bool c1 = procE(pa.y, ga.y, ma.y, in, v1);
        bool c2 = procE(pa.z, ga.z, ma.z, in, v2);
        bool c3 = procE(pa.w, ga.w, ma.w, in, v3);
        if (use_scr) {
            unsigned m0 = __ballot_sync(0xffffffffu, c0);
            unsigned m1 = __ballot_sync(0xffffffffu, c1);
            unsigned m2 = __ballot_sync(0xffffffffu, c2);
            unsigned m3 = __ballot_sync(0xffffffffu, c3);
            unsigned tot = __popc(m0) + __popc(m1) + __popc(m2) + __popc(m3);
            unsigned base = 0;
            if (lane == 0 && tot) base = atomicAdd(&s_cnt, tot);
            base = __shfl_sync(0xffffffffu, base, 0);
            unsigned s = base;
            if (c0) g_scr[rb + s + __popc(m0 & lt)] = v0; s += __popc(m0);
            if (c1) g_scr[rb + s + __popc(m1 & lt)] = v1; s += __popc(m1);
            if (c2) g_scr[rb + s + __popc(m2 & lt)] = v2; s += __popc(m2);
            if (c3) g_scr[rb + s + __popc(m3 & lt)] = v3;
        }
    }
    // scalar tail (n % 4), block 0 only
    if (blockIdx.x == 0) {
        for (int i = (n4 << 2) + tid; i < n; i += BLK) {
            float p = pred[i], g = gt[i], mm = mask[i];
            bool valid = mm > 0.5f;
            bool ispos = valid && (g > 0.5f);
            bool cand  = valid && !ispos && (p >= 0.5f);
            if (valid) valc++;
            if (ispos) posc++;
            if (cand) {
                int idx = min((int)(p * 32.0f), 31) - 16;
                sh[(idx >> 2) * BLK + tid] += 1u << ((idx & 3) << 3);
            }
            if (use_scr && (ispos || cand)) {
                unsigned o = atomicAdd(&s_cnt, 1u);
                g_scr[rb + o] = ispos ? -p : p;
            }
        }
    }
    __syncthreads();

    {   // staggered conflict-free u8 flush
        const int b     = tid & 15;
        const int chunk = tid >> 4;
        const int w     = (b >> 2) * BLK;
        const int shft  = (b & 3) << 3;
        unsigned s = 0;
#pragma unroll
        for (int jj = 0; jj < 16; jj++) {
            int j = chunk * 16 + ((jj + b) & 15);
            s += (sh[w + j] >> shft) & 0xFFu;
        }
        if (s) atomicAdd(&s_binsum[b], s);
    }

#pragma unroll
    for (int o = 16; o > 0; o >>= 1) {
        posc += __shfl_down_sync(0xffffffffu, posc, o);
        valc += __shfl_down_sync(0xffffffffu, valc, o);
    }
    if (lane == 0) { w_pc[tid >> 5] = posc; w_vc[tid >> 5] = valc; }
    __syncthreads();

    if (tid < NB1 && s_binsum[tid]) atomicAdd(&g_h1[tid], s_binsum[tid]);
    if (tid == 0) {
        unsigned pc = 0, vc = 0;
#pragma unroll
        for (int w = 0; w < BLK / 32; w++) { pc += w_pc[w]; vc += w_vc[w]; }
        if (pc) atomicAdd(&g_pos_cnt, pc);
        if (vc - pc) atomicAdd(&g_neg_cnt, vc - pc);
        g_cnt_blk[blockIdx.x] = s_cnt;
    }
}

// ---------------------------------------------------------------------------
// K2: sums + last-block finalize
// ---------------------------------------------------------------------------
__global__ void __launch_bounds__(BLK) k2_sums(
    const float4* __restrict__ pred4, const float4* __restrict__ gt4,
    const float4* __restrict__ mask4,
    const float* __restrict__ pred, const float* __restrict__ gt,
    const float* __restrict__ mask, int n, int cap, int use_scr,
    float* __restrict__ out)
{
    __shared__ unsigned int s_h1[NB1];
    __shared__ int          s_T1;
    __shared__ unsigned int s_c2[NB2];
    __shared__ float        s_s2[NB2];
    __shared__ unsigned int s_fc[NFB];
    __shared__ float        s_fs[NFB];
    __shared__ float        w_as[BLK / 32], w_ps[BLK / 32];
    __shared__ unsigned int s_isLast;

    const int tid = threadIdx.x;
    if (tid < NB1) s_h1[tid] = g_h1[tid];
    if (tid < NB2) { s_c2[tid] = 0u; s_s2[tid] = 0.0f; }
    for (int i = tid; i < NFB; i += BLK) { s_fc[i] = 0u; s_fs[i] = 0.0f; }
    __syncthreads();

    if (tid == 0) {
        long long k;
        s_T1 = find_T1(s_h1, g_pos_cnt, (long long)g_neg_cnt, k);
    }
    __syncthreads();
    const int T1 = s_T1;

    float mN = 1.0f, mP = 1.0f;
    int   eN = 0,    eP = 0;
    float asum = 0.0f, psum = 0.0f;
    bool wrote_fine = false;

    if (use_scr && T1 >= 16 && T1 < 32) {
        const long long rb  = (long long)blockIdx.x * (long long)cap;
        const unsigned  cnt = g_cnt_blk[blockIdx.x];
        auto hv = [&](float v) {
            if (v < 0.0f) {                      // positive
                float x = -v;
                if (x < 1e-37f) psum += fminf(-__logf(x), 100.0f);
                else            acc_log(x, mP, eP);
            } else {
                int b = min((int)(v * 32.0f), 31);
                if (b > T1) {
                    float x = 1.0f - v;
                    if (x < 1e-37f) asum += fminf(-__logf(x), 100.0f);
                    else            acc_log(x, mN, eN);
                } else if (b == T1) {
                    int b2 = (int)(v * 2048.0f) - T1 * 64;
                    b2 = max(0, min(b2, NB2 - 1));
                    atomicAdd(&s_c2[b2], 1u);
                    atomicAdd(&s_s2[b2], neg_loss_f(v));
                }
            }
        };
        const float4* s4 = (const float4*)&g_scr[rb];
        const unsigned c4 = cnt >> 2;
        for (unsigned j = tid; j < c4; j += BLK) {
            float4 v = s4[j];
            hv(v.x); hv(v.y); hv(v.z); hv(v.w);
        }
        for (unsigned j = (c4 << 2) + tid; j < cnt; j += BLK) hv(g_scr[rb + j]);
    } else if (use_scr && T1 == 1000) {
        const long long rb  = (long long)blockIdx.x * (long long)cap;
        const unsigned  cnt = g_cnt_blk[blockIdx.x];
        for (unsigned j = tid; j < cnt; j += BLK) {
            float v = g_scr[rb + j];
            if (v < 0.0f) {
                float x = -v;
                if (x < 1e-37f) psum += fminf(-__logf(x), 100.0f);
                else            acc_log(x, mP, eP);
            }
        }
    } else {
        // cold path: full re-read (no scratch or threshold below bin 16)
        wrote_fine = (T1 == -1);
        const int n4 = n >> 2;
        const int stp = gridDim.x * BLK;
        auto hfull = [&](float p, float g, float mm) {
            if (mm > 0.5f) {
                if (g > 0.5f) { psum += pos_loss_f(p); return; }
                if (T1 == 1000) return;
                if (T1 >= 16) {
                    int b = min((int)(p * 32.0f), 31);
                    if (b > T1) asum += neg_loss_f(p);
                    else if (b == T1) {
                        int b2 = (int)(p * 2048.0f) - T1 * 64;
                        b2 = max(0, min(b2, NB2 - 1));
                        atomicAdd(&s_c2[b2], 1u);
                        atomicAdd(&s_s2[b2], neg_loss_f(p));
                    }
                } else {
                    if (p >= 0.5f) asum += neg_loss_f(p);
                    else {
                        int fb = max(0, min((int)(p * 2048.0f), NFB - 1));
                        atomicAdd(&s_fc[fb], 1u);
                        atomicAdd(&s_fs[fb], neg_loss_f(p));
                    }
                }
            }
        };
        for (int ib = blockIdx.x * BLK; ib < n4; ib += stp) {
            int i = ib + tid;
            if (i < n4) {
                float4 p = pred4[i], g = gt4[i], m = mask4[i];
                hfull(p.x, g.x, m.x); hfull(p.y, g.y, m.y);
                hfull(p.z, g.z, m.z); hfull(p.w, g.w, m.w);
            }
        }
        if (blockIdx.x == 0) {
            for (int i = (n4 << 2) + tid; i < n; i += BLK)
                hfull(pred[i], gt[i], mask[i]);
        }
    }

    asum += finish_log(mN, eN);
    psum += finish_log(mP, eP);

#pragma unroll
    for (int o = 16; o > 0; o >>= 1) {
        asum += __shfl_down_sync(0xffffffffu, asum, o);
        psum += __shfl_down_sync(0xffffffffu, psum, o);
    }
    if ((tid & 31) == 0) { w_as[tid >> 5] = asum; w_ps[tid >> 5] = psum; }
    __syncthreads();

    if (tid < NB2 && s_c2[tid]) {
        atomicAdd(&g_h2c[tid], s_c2[tid]);
        atomicAdd(&g_h2s[tid], s_s2[tid]);
    }
    if (wrote_fine) {
        for (int i = tid; i < NFB; i += BLK) {
            if (s_fc[i]) { atomicAdd(&g_fc[i], s_fc[i]); atomicAdd(&g_fs[i], s_fs[i]); }
        }
    }
    if (tid == 0) {
        float as = 0.0f, ps = 0.0f;
#pragma unroll
        for (int w = 0; w < BLK / 32; w++) { as += w_as[w]; ps += w_ps[w]; }
        atomicAdd(&g_above_sum, (double)as);
        atomicAdd(&g_pos_sum, (double)ps);
    }

    // ---- last-block finalize (threadFenceReduction idiom) -----------------
    __threadfence();
    __syncthreads();
    if (tid == 0) {
        unsigned old = atomicAdd(&g_done, 1u);
        s_isLast = (old == gridDim.x - 1u) ? 1u : 0u;
    }
    __syncthreads();
    if (!s_isLast) return;

    // parallel preload of global totals into shared
    if (tid < NB2) {
        s_c2[tid] = g_h2c[tid];
        s_s2[tid] = g_h2s[tid];
    }
    for (int i = tid; i < NFB; i += BLK) { s_fc[i] = g_fc[i]; s_fs[i] = g_fs[i]; }
    __syncthreads();

    if (tid == 0) {
        unsigned pos = g_pos_cnt;
        long long k;
        int T1f = find_T1(s_h1, pos, (long long)g_neg_cnt, k);

        double nsum = 0.0;
        if (k > 0) {
            if (T1f >= 16 && T1f < 32) {
                long long cAbove1 = 0;
                for (int i = T1f + 1 - 16; i < NB1; i++) cAbove1 += (long long)s_h1[i];
                long long r = k - cAbove1;

                long long c2 = 0, cAbove2 = 0;
                double s2above = 0.0;
                int T2 = -1;
                for (int i = NB2 - 1; i >= 0; i--) {
                    long long cn = c2 + (long long)s_c2[i];
                    if (cn >= r) { T2 = i; cAbove2 = c2; break; }
                    s2above += (double)s_s2[i];
                    c2 = cn;
                }
                double part = 0.0;
                if (T2 >= 0 && s_c2[T2] > 0u) {
                    long long r2 = r - cAbove2;
                    if (r2 < 0) r2 = 0;
                    part = (double)s_s2[T2] * ((double)r2 / (double)s_c2[T2]);
                }
                nsum = g_above_sum + s2above + part;
            } else {
                // fine path: above_sum covers p>=0.5 candidates; take the
                // rest from the 1024 fine bins over [0,0.5)
                long long cand = 0;
                for (int i = 0; i < NB1; i++) cand += (long long)s_h1[i];
                long long r = k - cand;
                long long c2 = 0, cAbove2 = 0;
                double s2above = 0.0;
                int T2 = -1;
                for (int i = NFB - 1; i >= 0; i--) {
                    long long cn = c2 + (long long)s_fc[i];
                    if (cn >= r) { T2 = i; cAbove2 = c2; break; }
                    s2above += (double)s_fs[i];
                    c2 = cn;
                }
                double part = 0.0;
                if (T2 >= 0 && s_fc[T2] > 0u) {
                    long long r2 = r - cAbove2;
                    if (r2 < 0) r2 = 0;
                    part = (double)s_fs[T2] * ((double)r2 / (double)s_fc[T2]);
                }
                nsum = g_above_sum + s2above + part;
            }
        }

        double denom = (double)pos + (double)k + 1e-6;
        out[0] = (float)((g_pos_sum + nsum) / denom);
    }
    __syncthreads();   // finalize reads done before reset

    // reset all globals for graph replay
    if (tid < NB1) g_h1[tid] = 0u;
    if (tid < NB2) { g_h2c[tid] = 0u; g_h2s[tid] = 0.0f; }
    for (int i = tid; i < NFB; i += BLK) { g_fc[i] = 0u; g_fs[i] = 0.0f; }
    if (tid == 0) {
        g_pos_cnt   = 0u;
        g_neg_cnt   = 0u;
        g_pos_sum   = 0.0;
        g_above_sum = 0.0;
        g_done      = 0u;
    }
}

// ---------------------------------------------------------------------------
extern "C" void kernel_launch(void* const* d_in, const int* in_sizes, int n_in,
                              void* d_out, int out_size)
{
    const float* pred = (const float*)d_in[0];
    const float* gt   = (const float*)d_in[1];
    const float* mask = (const float*)d_in[2];
    float* out = (float*)d_out;
    const int n = in_sizes[0];

    const float4* pred4 = (const float4*)pred;
    const float4* gt4   = (const float4*)gt;
    const float4* mask4 = (const float4*)mask;

    int n4 = n >> 2;
    int grid = (n4 + BLK - 1) / BLK;
    if (grid > GRID_CAP) grid = GRID_CAP;
    if (grid < 1) grid = 1;

    int iters = (n4 + grid * BLK - 1) / (grid * BLK);
    long long cap = (long long)iters * BLK * 4 + 8;
    int use_scr = ((long long)grid * cap <= (long long)SCR_SZ) ? 1 : 0;

    k1_scan<<<grid, BLK>>>(pred4, gt4, mask4, pred, gt, mask, n, (int)cap, use_scr);
    k2_sums<<<grid, BLK>>>(pred4, gt4, mask4, pred, gt, mask, n, (int)cap, use_scr, out);
}

// round 8
// speedup vs baseline: 1.0358x; 1.0358x over previous
#include <cuda_runtime.h>

// ---------------------------------------------------------------------------
// MaskedBalancedBCELoss — 2-kernel pipeline.
//  K1 (one 157 MB streaming read): counts pos/valid in regs; u8-packed 16-bin
//     histogram of p over CANDIDATES only (negatives with p>=0.5);
//     ballot-compacts tagged candidates (negatives as +p, positives as -p)
//     into per-block scratch regions (~25 MB).
//  K2: derives threshold bin T1; one MLP-4 unrolled pass over scratch feeding
//      a SINGLE merged log-sum accumulator (mantissa-product + exponent):
//      positives and negative bins > T1 both accumulate; bin == T1 -> exact
//      log + 64-sub-bin count/sum hist (rare). Cold fallback (T1 below bin 16
//      or no scratch): full re-read with 1024 fine bins. The LAST block
//      (fence + counter) finalizes and resets globals (graph-replay safe).
// ---------------------------------------------------------------------------

#define NB1 16             // bins 16..31 of (int)(p*32)
#define NB2 64
#define NFB 1024           // fine bins over [0,0.5) for the cold fallback
#define BLK 256
#define GRID_CAP 888
#define SCR_SZ (16u << 20) // 16M floats = 64 MB

__device__ __align__(16) float g_scr[SCR_SZ];
__device__ unsigned int g_cnt_blk[GRID_CAP];
__device__ unsigned int g_h1[NB1];
__device__ unsigned int g_h2c[NB2];
__device__ float        g_h2s[NB2];
__device__ unsigned int g_fc[NFB];
__device__ float        g_fs[NFB];
__device__ unsigned int g_pos_cnt;
__device__ unsigned int g_neg_cnt;
__device__ double       g_sum_main;   // positives + above-threshold negatives
__device__ unsigned int g_done;

// Cephes-style natural log, pure FMA/ALU (no MUFU). ~1-2 ulp on normals.
__device__ __forceinline__ float fast_log(float x) {
    int   i  = __float_as_int(x);
    int   e  = ((i >> 23) & 0xFF) - 127;
    float m  = __int_as_float((i & 0x007FFFFF) | 0x3F800000);
    if (m > 1.41421356f) { m *= 0.5f; e += 1; }
    float t  = m - 1.0f;
    float z  = t * t;
    float P  = 7.0376836292e-2f;
    P = P * t - 1.1514610310e-1f;
    P = P * t + 1.1676998740e-1f;
    P = P * t - 1.2420140846e-1f;
    P = P * t + 1.4249322787e-1f;
    P = P * t - 1.6668057665e-1f;
    P = P * t + 2.0000714765e-1f;
    P = P * t - 2.4999993993e-1f;
    P = P * t + 3.3333331174e-1f;
    float fe = (float)e;
    float y  = t * z * P;
    y += fe * -2.12194440e-4f;
    y -= 0.5f * z;
    float r  = t + y;
    r += fe * 0.693359375f;
    return r;
}
__device__ __forceinline__ float pos_loss_f(float p) { return fminf(-fast_log(p), 100.0f); }
__device__ __forceinline__ float neg_loss_f(float p) { return fminf(-fast_log(1.0f - p), 100.0f); }

__device__ __forceinline__ float finish_log(float m, int e) {
    return -(fast_log(m) + (float)e * 0.69314718056f);
}

// Threshold bin. 1000 if k==0; -1 if below bin 16 (cold); else T1 in [16,31].
__device__ __forceinline__ int find_T1(const unsigned* h1, unsigned pos,
                                       long long negtot, long long& k_out) {
    long long k3p = 3LL * (long long)pos;
    long long k = (pos == 0u) ? 0LL : (negtot < k3p ? negtot : k3p);
    k_out = k;
    if (k == 0) return 1000;
    long long c = 0;
    for (int i = NB1 - 1; i >= 0; i--) {
        c += (long long)h1[i];
        if (c >= k) return i + 16;
    }
    return -1;
}

// ---------------------------------------------------------------------------
// K1: stream, classify, candidate histogram, compact.  (unchanged from R7)
// ---------------------------------------------------------------------------
__global__ void __launch_bounds__(BLK, 6) k1_scan(
    const float4* __restrict__ pred4, const float4* __restrict__ gt4,
    const float4* __restrict__ mask4,
    const float* __restrict__ pred, const float* __restrict__ gt,
    const float* __restrict__ mask, int n, int cap, int use_scr)
{
    __shared__ unsigned int sh[4 * BLK];
    __shared__ unsigned int s_binsum[NB1];
    __shared__ unsigned int s_cnt;
    __shared__ unsigned int w_pc[BLK / 32], w_vc[BLK / 32];

    const int tid  = threadIdx.x;
    const int lane = tid & 31;
    const unsigned lt = (1u << lane) - 1u;

#pragma unroll
    for (int w = 0; w < 4; w++) sh[w * BLK + tid] = 0u;
    if (tid < NB1) s_binsum[tid] = 0u;
    if (tid == 0) s_cnt = 0u;
    __syncthreads();

    unsigned int posc = 0, valc = 0;
    const int n4   = n >> 2;
    const int step = gridDim.x * BLK;
    const long long rb = (long long)blockIdx.x * (long long)cap;

    auto procE = [&](float p, float g, float mm, bool in, float& v) -> bool {
        bool valid = in && (mm > 0.5f);
        bool ispos = valid && (g > 0.5f);
        valc += valid ? 1u : 0u;
        posc += ispos ? 1u : 0u;
        v = ispos ? -p : p;
        bool cand = valid && !(g > 0.5f) && (p >= 0.5f);
        if (cand) {
            int idx = min((int)(p * 32.0f), 31) - 16;
            sh[(idx >> 2) * BLK + tid] += 1u << ((idx & 3) << 3);
        }
        return ispos || cand;
    };

    int ibase = blockIdx.x * BLK;
    while (ibase + step + BLK <= n4) {
        int i0 = ibase + tid, i1 = i0 + step;
        float4 pa = __ldcs(&pred4[i0]), ga = __ldcs(&gt4[i0]), ma = __ldcs(&mask4[i0]);
        float4 pb = __ldcs(&pred4[i1]), gb = __ldcs(&gt4[i1]), mb = __ldcs(&mask4[i1]);
        float v0, v1, v2, v3, v4, v5, v6, v7;
        bool c0 = procE(pa.x, ga.x, ma.x, true, v0);
        bool c1 = procE(pa.y, ga.y, ma.y, true, v1);
        bool c2 = procE(pa.z, ga.z, ma.z, true, v2);
        bool c3 = procE(pa.w, ga.w, ma.w, true, v3);
        bool c4 = procE(pb.x, gb.x, mb.x, true, v4);
        bool c5 = procE(pb.y, gb.y, mb.y, true, v5);
        bool c6 = procE(pb.z, gb.z, mb.z, true, v6);
        bool c7 = procE(pb.w, gb.w, mb.w, true, v7);
        if (use_scr) {
            unsigned m0 = __ballot_sync(0xffffffffu, c0);
            unsigned m1 = __ballot_sync(0xffffffffu, c1);
            unsigned m2 = __ballot_sync(0xffffffffu, c2);
            unsigned m3 = __ballot_sync(0xffffffffu, c3);
            unsigned m4 = __ballot_sync(0xffffffffu, c4);
            unsigned m5 = __ballot_sync(0xffffffffu, c5);
            unsigned m6 = __ballot_sync(0xffffffffu, c6);
            unsigned m7 = __ballot_sync(0xffffffffu, c7);
            unsigned tot = __popc(m0) + __popc(m1) + __popc(m2) + __popc(m3)
                         + __popc(m4) + __popc(m5) + __popc(m6) + __popc(m7);
            unsigned base = 0;
            if (lane == 0 && tot) base = atomicAdd(&s_cnt, tot);
            base = __shfl_sync(0xffffffffu, base, 0);
            unsigned s = base;
            if (c0) g_scr[rb + s + __popc(m0 & lt)] = v0; s += __popc(m0);
            if (c1) g_scr[rb + s + __popc(m1 & lt)] = v1; s += __popc(m1);
            if (c2) g_scr[rb + s + __popc(m2 & lt)] = v2; s += __popc(m2);
            if (c3) g_scr[rb + s + __popc(m3 & lt)] = v3; s += __popc(m3);
            if (c4) g_scr[rb + s + __popc(m4 & lt)] = v4; s += __popc(m4);
            if (c5) g_scr[rb + s + __popc(m5 & lt)] = v5; s += __popc(m5);
            if (c6) g_scr[rb + s + __popc(m6 & lt)] = v6; s += __popc(m6);
            if (c7) g_scr[rb + s + __popc(m7 & lt)] = v7;
        }
        ibase += 2 * step;
    }
    for (; ibase < n4; ibase += step) {
        int i = ibase + tid;
        bool in = i < n4;
        float4 pa = in ? __ldcs(&pred4[i]) : make_float4(0.f, 0.f, 0.f, 0.f);
        float4 ga = in ? __ldcs(&gt4[i])   : make_float4(1.f, 1.f, 1.f, 1.f);
        float4 ma = in ? __ldcs(&mask4[i]) : make_float4(0.f, 0.f, 0.f, 0.f);
        float v0, v1, v2, v3;
        bool c0 = procE(pa.x, ga.x, ma.x, in, v0);
        bool c1 = procE(pa.y, ga.y, ma.y, in, v1);
        bool c2 = procE(pa.z, ga.z, ma.z, in, v2);
        bool c3 = procE(pa.w, ga.w, ma.w, in, v3);
        if (use_scr) {
            unsigned m0 = __ballot_sync(0xffffffffu, c0);
            unsigned m1 = __ballot_sync(0xffffffffu, c1);
            unsigned m2 = __ballot_sync(0xffffffffu, c2);
            unsigned m3 = __ballot_sync(0xffffffffu, c3);
            unsigned tot = __popc(m0) + __popc(m1) + __popc(m2) + __popc(m3);
            unsigned base = 0;
            if (lane == 0 && tot) base = atomicAdd(&s_cnt, tot);
            base = __shfl_sync(0xffffffffu, base, 0);
            unsigned s = base;
            if (c0) g_scr[rb + s + __popc(m0 & lt)] = v0; s += __popc(m0);
            if (c1) g_scr[rb + s + __popc(m1 & lt)] = v1; s += __popc(m1);
            if (c2) g_scr[rb + s + __popc(m2 & lt)] = v2; s += __popc(m2);
            if (c3) g_scr[rb + s + __popc(m3 & lt)] = v3;
        }
    }
    if (blockIdx.x == 0) {
        for (int i = (n4 << 2) + tid; i < n; i += BLK) {
            float p = pred[i], g = gt[i], mm = mask[i];
            bool valid = mm > 0.5f;
            bool ispos = valid && (g > 0.5f);
            bool cand  = valid && !ispos && (p >= 0.5f);
            if (valid) valc++;
            if (ispos) posc++;
            if (cand) {
                int idx = min((int)(p * 32.0f), 31) - 16;
                sh[(idx >> 2) * BLK + tid] += 1u << ((idx & 3) << 3);
            }
            if (use_scr && (ispos || cand)) {
                unsigned o = atomicAdd(&s_cnt, 1u);
                g_scr[rb + o] = ispos ? -p : p;
            }
        }
    }
    __syncthreads();

    {
        const int b     = tid & 15;
        const int chunk = tid >> 4;
        const int w     = (b >> 2) * BLK;
        const int shft  = (b & 3) << 3;
        unsigned s = 0;
#pragma unroll
        for (int jj = 0; jj < 16; jj++) {
            int j = chunk * 16 + ((jj + b) & 15);
            s += (sh[w + j] >> shft) & 0xFFu;
        }
        if (s) atomicAdd(&s_binsum[b], s);
    }

#pragma unroll
    for (int o = 16; o > 0; o >>= 1) {
        posc += __shfl_down_sync(0xffffffffu, posc, o);
        valc += __shfl_down_sync(0xffffffffu, valc, o);
    }
    if (lane == 0) { w_pc[tid >> 5] = posc; w_vc[tid >> 5] = valc; }
    __syncthreads();

    if (tid < NB1 && s_binsum[tid]) atomicAdd(&g_h1[tid], s_binsum[tid]);
    if (tid == 0) {
        unsigned pc = 0, vc = 0;
#pragma unroll
        for (int w = 0; w < BLK / 32; w++) { pc += w_pc[w]; vc += w_vc[w]; }
        if (pc) atomicAdd(&g_pos_cnt, pc);
        if (vc - pc) atomicAdd(&g_neg_cnt, vc - pc);
        g_cnt_blk[blockIdx.x] = s_cnt;
    }
}

// ---------------------------------------------------------------------------
// K2: merged log-sum over scratch (MLP-4) + last-block finalize
// ---------------------------------------------------------------------------
__global__ void __launch_bounds__(BLK) k2_sums(
    const float4* __restrict__ pred4, const float4* __restrict__ gt4,
    const float4* __restrict__ mask4,
    const float* __restrict__ pred, const float* __restrict__ gt,
    const float* __restrict__ mask, int n, int cap, int use_scr,
    float* __restrict__ out)
{
    __shared__ unsigned int s_h1[NB1];
    __shared__ int          s_T1;
    __shared__ unsigned int s_c2[NB2];
    __shared__ float        s_s2[NB2];
    __shared__ unsigned int s_fc[NFB];
    __shared__ float        s_fs[NFB];
    __shared__ float        w_es[BLK / 32];
    __shared__ unsigned int s_isLast;

    const int tid = threadIdx.x;
    if (tid < NB1) s_h1[tid] = g_h1[tid];
    if (tid < NB2) { s_c2[tid] = 0u; s_s2[tid] = 0.0f; }
    __syncthreads();

    if (tid == 0) {
        long long k;
        s_T1 = find_T1(s_h1, g_pos_cnt, (long long)g_neg_cnt, k);
    }
    __syncthreads();
    const int T1 = s_T1;

    float mA = 1.0f;     // merged mantissa product (positives + above-T1 negs)
    int   eA = 0;
    float esum = 0.0f;   // exact-path extras
    bool wrote_fine = false;

    // merged per-element handler (warm path). Branchless except rare T1 bin.
    auto pv = [&](float v) {
        bool isPos = v < 0.0f;
        float x = isPos ? -v : 1.0f - v;
        int b = min((int)(v * 32.0f), 31);
        if (!isPos && b == T1) {                    // rare (~5%)
            int b2 = (int)(v * 2048.0f) - T1 * 64;
            b2 = max(0, min(b2, NB2 - 1));
            atomicAdd(&s_c2[b2], 1u);
            atomicAdd(&s_s2[b2], neg_loss_f(v));
        }
        bool take = isPos || (b > T1);
        float xm = take ? x : 1.0f;
        if (xm < 1e-37f) { esum += fminf(-__logf(xm), 100.0f); xm = 1.0f; }
        mA *= xm;
        int i = __float_as_int(mA);
        eA += ((i >> 23) & 0xFF) - 127;
        mA = __int_as_float((i & 0x807FFFFFu) | 0x3F800000u);
    };

    if (use_scr && T1 >= 16) {
        // warm path (T1 in [16,31], or T1==1000 -> only positives taken)
        const long long rb  = (long long)blockIdx.x * (long long)cap;
        const unsigned  cnt = g_cnt_blk[blockIdx.x];
        const float4*   s4  = (const float4*)&g_scr[rb];
        const unsigned  c4  = cnt >> 2;
        unsigned j = tid;
        for (; j + 3u * BLK < c4; j += 4u * BLK) {      // MLP-4
            float4 a  = s4[j];
            float4 b4 = s4[j + BLK];
            float4 c  = s4[j + 2u * BLK];
            float4 d  = s4[j + 3u * BLK];
            pv(a.x);  pv(a.y);  pv(a.z);  pv(a.w);
            pv(b4.x); pv(b4.y); pv(b4.z); pv(b4.w);
            pv(c.x);  pv(c.y);  pv(c.z);  pv(c.w);
            pv(d.x);  pv(d.y);  pv(d.z);  pv(d.w);
        }
        for (; j < c4; j += BLK) {
            float4 a = s4[j];
            pv(a.x); pv(a.y); pv(a.z); pv(a.w);
        }
        for (unsigned t = (c4 << 2) + tid; t < cnt; t += BLK) pv(g_scr[rb + t]);
    } else {
        // cold path: full re-read (no scratch, or threshold below bin 16)
        wrote_fine = (T1 == -1);
        if (T1 == -1 || !use_scr) {
            for (int i = tid; i < NFB; i += BLK) { s_fc[i] = 0u; s_fs[i] = 0.0f; }
            __syncthreads();
        }
        const int n4 = n >> 2;
        const int stp = gridDim.x * BLK;
        auto hfull = [&](float p, float g, float mm) {
            if (mm > 0.5f) {
                if (g > 0.5f) { esum += pos_loss_f(p); return; }
                if (T1 == 1000) return;
                if (T1 >= 16) {
                    int b = min((int)(p * 32.0f), 31);
                    if (b > T1) esum += neg_loss_f(p);
                    else if (b == T1) {
                        int b2 = (int)(p * 2048.0f) - T1 * 64;
                        b2 = max(0, min(b2, NB2 - 1));
                        atomicAdd(&s_c2[b2], 1u);
                        atomicAdd(&s_s2[b2], neg_loss_f(p));
                    }
                } else {
                    if (p >= 0.5f) esum += neg_loss_f(p);
                    else {
                        int fb = max(0, min((int)(p * 2048.0f), NFB - 1));
                        atomicAdd(&s_fc[fb], 1u);
                        atomicAdd(&s_fs[fb], neg_loss_f(p));
                    }
                }
            }
        };
        for (int ib = blockIdx.x * BLK; ib < n4; ib += stp) {
            int i = ib + tid;
            if (i < n4) {
                float4 p = pred4[i], g = gt4[i], m = mask4[i];
                hfull(p.x, g.x, m.x); hfull(p.y, g.y, m.y);
                hfull(p.z, g.z, m.z); hfull(p.w, g.w, m.w);
            }
        }
        if (blockIdx.x == 0) {
            for (int i = (n4 << 2) + tid; i < n; i += BLK)
                hfull(pred[i], gt[i], mask[i]);
        }
        __syncthreads();
        if (wrote_fine) {
            for (int i = tid; i < NFB; i += BLK) {
                if (s_fc[i]) { atomicAdd(&g_fc[i], s_fc[i]); atomicAdd(&g_fs[i], s_fs[i]); }
            }
        }
    }

    esum += finish_log(mA, eA);

#pragma unroll
    for (int o = 16; o > 0; o >>= 1)
        esum += __shfl_down_sync(0xffffffffu, esum, o);
    if ((tid & 31) == 0) w_es[tid >> 5] = esum;
    __syncthreads();

    if (tid < NB2 && s_c2[tid]) {
        atomicAdd(&g_h2c[tid], s_c2[tid]);
        atomicAdd(&g_h2s[tid], s_s2[tid]);
    }
    if (tid == 0) {
        float es = 0.0f;
#pragma unroll
        for (int w = 0; w < BLK / 32; w++) es += w_es[w];
        atomicAdd(&g_sum_main, (double)es);
    }

    // ---- last-block finalize ----------------------------------------------
    __threadfence();
    __syncthreads();
    if (tid == 0) {
        unsigned old = atomicAdd(&g_done, 1u);
        s_isLast = (old == gridDim.x - 1u) ? 1u : 0u;
    }
    __syncthreads();
    if (!s_isLast) return;

    // parallel preload of global totals
    if (tid < NB2) { s_c2[tid] = g_h2c[tid]; s_s2[tid] = g_h2s[tid]; }
    if (T1 == -1) {
        for (int i = tid; i < NFB; i += BLK) { s_fc[i] = g_fc[i]; s_fs[i] = g_fs[i]; }
    }
    __syncthreads();

    if (tid == 0) {
        unsigned pos = g_pos_cnt;
        long long k;
        int T1f = find_T1(s_h1, pos, (long long)g_neg_cnt, k);

        double extra = 0.0;
        if (k > 0) {
            if (T1f >= 16 && T1f < 32) {
                long long cAbove1 = 0;
                for (int i = T1f + 1 - 16; i < NB1; i++) cAbove1 += (long long)s_h1[i];
                long long r = k - cAbove1;

                long long c2 = 0, cAbove2 = 0;
                double s2above = 0.0;
                int T2 = -1;
                for (int i = NB2 - 1; i >= 0; i--) {
                    long long cn = c2 + (long long)s_c2[i];
                    if (cn >= r) { T2 = i; cAbove2 = c2; break; }
                    s2above += (double)s_s2[i];
                    c2 = cn;
                }
                double part = 0.0;
                if (T2 >= 0 && s_c2[T2] > 0u) {
                    long long r2 = r - cAbove2;
                    if (r2 < 0) r2 = 0;
                    part = (double)s_s2[T2] * ((double)r2 / (double)s_c2[T2]);
                }
                extra = s2above + part;
            } else if (T1f == -1) {
                long long cand = 0;
                for (int i = 0; i < NB1; i++) cand += (long long)s_h1[i];
                long long r = k - cand;
                long long c2 = 0, cAbove2 = 0;
                double s2above = 0.0;
                int T2 = -1;
                for (int i = NFB - 1; i >= 0; i--) {
                    long long cn = c2 + (long long)s_fc[i];
                    if (cn >= r) { T2 = i; cAbove2 = c2; break; }
                    s2above += (double)s_fs[i];
                    c2 = cn;
                }
                double part = 0.0;
                if (T2 >= 0 && s_fc[T2] > 0u) {
                    long long r2 = r - cAbove2;
                    if (r2 < 0) r2 = 0;
                    part = (double)s_fs[T2] * ((double)r2 / (double)s_fc[T2]);
                }
                extra = s2above + part;
            }
        }

        double denom = (double)pos + (double)k + 1e-6;
        out[0] = (float)((g_sum_main + extra) / denom);
    }
    __syncthreads();

    // reset globals for graph replay
    if (tid < NB1) g_h1[tid] = 0u;
    if (tid < NB2) { g_h2c[tid] = 0u; g_h2s[tid] = 0.0f; }
    for (int i = tid; i < NFB; i += BLK) { g_fc[i] = 0u; g_fs[i] = 0.0f; }
    if (tid == 0) {
        g_pos_cnt  = 0u;
        g_neg_cnt  = 0u;
        g_sum_main = 0.0;
        g_done     = 0u;
    }
}

// ---------------------------------------------------------------------------
extern "C" void kernel_launch(void* const* d_in, const int* in_sizes, int n_in,
                              void* d_out, int out_size)
{
    const float* pred = (const float*)d_in[0];
    const float* gt   = (const float*)d_in[1];
    const float* mask = (const float*)d_in[2];
    float* out = (float*)d_out;
    const int n = in_sizes[0];

    const float4* pred4 = (const float4*)pred;
    const float4* gt4   = (const float4*)gt;
    const float4* mask4 = (const float4*)mask;

    int n4 = n >> 2;
    int grid = (n4 + BLK - 1) / BLK;
    if (grid > GRID_CAP) grid = GRID_CAP;
    if (grid < 1) grid = 1;

    int iters = (n4 + grid * BLK - 1) / (grid * BLK);
    long long cap = (long long)iters * BLK * 4 + 8;
    int use_scr = ((long long)grid * cap <= (long long)SCR_SZ) ? 1 : 0;

    k1_scan<<<grid, BLK>>>(pred4, gt4, mask4, pred, gt, mask, n, (int)cap, use_scr);
    k2_sums<<<grid, BLK>>>(pred4, gt4, mask4, pred, gt, mask, n, (int)cap, use_scr, out);
}

// round 9
// speedup vs baseline: 1.1105x; 1.0721x over previous
#include <cuda_runtime.h>

// ---------------------------------------------------------------------------
// MaskedBalancedBCELoss — 2-kernel pipeline.
//  K1 (one 157 MB streaming read): counts pos/valid in regs; u8-packed 16-bin
//     histogram of p over CANDIDATES (negatives with p>=0.5); ballot-compacts
//     tagged candidates (negatives +p, positives -p) into per-block scratch.
//  K2: derives threshold bin T1; one pass over scratch with a merged log-sum
//      (mantissa-product + exponent, 2-way ILP). Bin == T1 -> CHEAP sub-bin
//      (count, sum-of-p) shared atomics (no log in the hot path); the
//      finalize reconstructs sub-bin loss sums as cnt*(-log(1-mean_p)).
//      Cold fallback: full re-read with 1024 fine (count,sum-p) bins.
//      LAST block (fence+counter) finalizes and resets globals.
// ---------------------------------------------------------------------------

#define NB1 16             // bins 16..31 of (int)(p*32)
#define NB2 64
#define NFB 1024           // fine bins over [0,0.5) for the cold fallback
#define BLK 256
#define GRID_CAP 888
#define SCR_SZ (16u << 20) // 16M floats = 64 MB

__device__ __align__(16) float g_scr[SCR_SZ];
__device__ unsigned int g_cnt_blk[GRID_CAP];
__device__ unsigned int g_h1[NB1];
__device__ unsigned int g_h2c[NB2];
__device__ float        g_h2s[NB2];   // Σp per sub-bin
__device__ unsigned int g_fc[NFB];
__device__ float        g_fs[NFB];    // Σp per fine bin
__device__ unsigned int g_pos_cnt;
__device__ unsigned int g_neg_cnt;
__device__ double       g_sum_main;   // positives + above-threshold negatives
__device__ unsigned int g_done;

// Cephes-style natural log, pure FMA/ALU (no MUFU). ~1-2 ulp on normals.
__device__ __forceinline__ float fast_log(float x) {
    int   i  = __float_as_int(x);
    int   e  = ((i >> 23) & 0xFF) - 127;
    float m  = __int_as_float((i & 0x007FFFFF) | 0x3F800000);
    if (m > 1.41421356f) { m *= 0.5f; e += 1; }
    float t  = m - 1.0f;
    float z  = t * t;
    float P  = 7.0376836292e-2f;
    P = P * t - 1.1514610310e-1f;
    P = P * t + 1.1676998740e-1f;
    P = P * t - 1.2420140846e-1f;
    P = P * t + 1.4249322787e-1f;
    P = P * t - 1.6668057665e-1f;
    P = P * t + 2.0000714765e-1f;
    P = P * t - 2.4999993993e-1f;
    P = P * t + 3.3333331174e-1f;
    float fe = (float)e;
    float y  = t * z * P;
    y += fe * -2.12194440e-4f;
    y -= 0.5f * z;
    float r  = t + y;
    r += fe * 0.693359375f;
    return r;
}
__device__ __forceinline__ float pos_loss_f(float p) { return fminf(-fast_log(p), 100.0f); }
__device__ __forceinline__ float neg_loss_f(float p) { return fminf(-fast_log(1.0f - p), 100.0f); }

__device__ __forceinline__ float finish_log(float m, int e) {
    return -(fast_log(m) + (float)e * 0.69314718056f);
}

// Threshold bin. 1000 if k==0; -1 if below bin 16 (cold); else T1 in [16,31].
__device__ __forceinline__ int find_T1(const unsigned* h1, unsigned pos,
                                       long long negtot, long long& k_out) {
    long long k3p = 3LL * (long long)pos;
    long long k = (pos == 0u) ? 0LL : (negtot < k3p ? negtot : k3p);
    k_out = k;
    if (k == 0) return 1000;
    long long c = 0;
    for (int i = NB1 - 1; i >= 0; i--) {
        c += (long long)h1[i];
        if (c >= k) return i + 16;
    }
    return -1;
}

// ---------------------------------------------------------------------------
// K1: stream, classify, candidate histogram, compact.  (unchanged)
// ---------------------------------------------------------------------------
__global__ void __launch_bounds__(BLK, 6) k1_scan(
    const float4* __restrict__ pred4, const float4* __restrict__ gt4,
    const float4* __restrict__ mask4,
    const float* __restrict__ pred, const float* __restrict__ gt,
    const float* __restrict__ mask, int n, int cap, int use_scr)
{
    __shared__ unsigned int sh[4 * BLK];
    __shared__ unsigned int s_binsum[NB1];
    __shared__ unsigned int s_cnt;
    __shared__ unsigned int w_pc[BLK / 32], w_vc[BLK / 32];

    const int tid  = threadIdx.x;
    const int lane = tid & 31;
    const unsigned lt = (1u << lane) - 1u;

#pragma unroll
    for (int w = 0; w < 4; w++) sh[w * BLK + tid] = 0u;
    if (tid < NB1) s_binsum[tid] = 0u;
    if (tid == 0) s_cnt = 0u;
    __syncthreads();

    unsigned int posc = 0, valc = 0;
    const int n4   = n >> 2;
    const int step = gridDim.x * BLK;
    const long long rb = (long long)blockIdx.x * (long long)cap;

    auto procE = [&](float p, float g, float mm, bool in, float& v) -> bool {
        bool valid = in && (mm > 0.5f);
        bool ispos = valid && (g > 0.5f);
        valc += valid ? 1u : 0u;
        posc += ispos ? 1u : 0u;
        v = ispos ? -p : p;
        bool cand = valid && !(g > 0.5f) && (p >= 0.5f);
        if (cand) {
            int idx = min((int)(p * 32.0f), 31) - 16;
            sh[(idx >> 2) * BLK + tid] += 1u << ((idx & 3) << 3);
        }
        return ispos || cand;
    };

    int ibase = blockIdx.x * BLK;
    while (ibase + step + BLK <= n4) {
        int i0 = ibase + tid, i1 = i0 + step;
        float4 pa = __ldcs(&pred4[i0]), ga = __ldcs(&gt4[i0]), ma = __ldcs(&mask4[i0]);
        float4 pb = __ldcs(&pred4[i1]), gb = __ldcs(&gt4[i1]), mb = __ldcs(&mask4[i1]);
        float v0, v1, v2, v3, v4, v5, v6, v7;
        bool c0 = procE(pa.x, ga.x, ma.x, true, v0);
        bool c1 = procE(pa.y, ga.y, ma.y, true, v1);
        bool c2 = procE(pa.z, ga.z, ma.z, true, v2);
        bool c3 = procE(pa.w, ga.w, ma.w, true, v3);
        bool c4 = procE(pb.x, gb.x, mb.x, true, v4);
        bool c5 = procE(pb.y, gb.y, mb.y, true, v5);
        bool c6 = procE(pb.z, gb.z, mb.z, true, v6);
        bool c7 = procE(pb.w, gb.w, mb.w, true, v7);
        if (use_scr) {
            unsigned m0 = __ballot_sync(0xffffffffu, c0);
            unsigned m1 = __ballot_sync(0xffffffffu, c1);
            unsigned m2 = __ballot_sync(0xffffffffu, c2);
            unsigned m3 = __ballot_sync(0xffffffffu, c3);
            unsigned m4 = __ballot_sync(0xffffffffu, c4);
            unsigned m5 = __ballot_sync(0xffffffffu, c5);
            unsigned m6 = __ballot_sync(0xffffffffu, c6);
            unsigned m7 = __ballot_sync(0xffffffffu, c7);
            unsigned tot = __popc(m0) + __popc(m1) + __popc(m2) + __popc(m3)
                         + __popc(m4) + __popc(m5) + __popc(m6) + __popc(m7);
            unsigned base = 0;
            if (lane == 0 && tot) base = atomicAdd(&s_cnt, tot);
            base = __shfl_sync(0xffffffffu, base, 0);
            unsigned s = base;
            if (c0) g_scr[rb + s + __popc(m0 & lt)] = v0; s += __popc(m0);
            if (c1) g_scr[rb + s + __popc(m1 & lt)] = v1; s += __popc(m1);
            if (c2) g_scr[rb + s + __popc(m2 & lt)] = v2; s += __popc(m2);
            if (c3) g_scr[rb + s + __popc(m3 & lt)] = v3; s += __popc(m3);
            if (c4) g_scr[rb + s + __popc(m4 & lt)] = v4; s += __popc(m4);
            if (c5) g_scr[rb + s + __popc(m5 & lt)] = v5; s += __popc(m5);
            if (c6) g_scr[rb + s + __popc(m6 & lt)] = v6; s += __popc(m6);
            if (c7) g_scr[rb + s + __popc(m7 & lt)] = v7;
        }
        ibase += 2 * step;
    }
    for (; ibase < n4; ibase += step) {
        int i = ibase + tid;
        bool in = i < n4;
        float4 pa = in ? __ldcs(&pred4[i]) : make_float4(0.f, 0.f, 0.f, 0.f);
        float4 ga = in ? __ldcs(&gt4[i])   : make_float4(1.f, 1.f, 1.f, 1.f);
        float4 ma = in ? __ldcs(&mask4[i]) : make_float4(0.f, 0.f, 0.f, 0.f);
        float v0, v1, v2, v3;
        bool c0 = procE(pa.x, ga.x, ma.x, in, v0);
        bool c1 = procE(pa.y, ga.y, ma.y, in, v1);
        bool c2 = procE(pa.z, ga.z, ma.z, in, v2);
        bool c3 = procE(pa.w, ga.w, ma.w, in, v3);
        if (use_scr) {
            unsigned m0 = __ballot_sync(0xffffffffu, c0);
            unsigned m1 = __ballot_sync(0xffffffffu, c1);
            unsigned m2 = __ballot_sync(0xffffffffu, c2);
            unsigned m3 = __ballot_sync(0xffffffffu, c3);
            unsigned tot = __popc(m0) + __popc(m1) + __popc(m2) + __popc(m3);
            unsigned base = 0;
            if (lane == 0 && tot) base = atomicAdd(&s_cnt, tot);
            base = __shfl_sync(0xffffffffu, base, 0);
            unsigned s = base;
            if (c0) g_scr[rb + s + __popc(m0 & lt)] = v0; s += __popc(m0);
            if (c1) g_scr[rb + s + __popc(m1 & lt)] = v1; s += __popc(m1);
            if (c2) g_scr[rb + s + __popc(m2 & lt)] = v2; s += __popc(m2);
            if (c3) g_scr[rb + s + __popc(m3 & lt)] = v3;
        }
    }
    if (blockIdx.x == 0) {
        for (int i = (n4 << 2) + tid; i < n; i += BLK) {
            float p = pred[i], g = gt[i], mm = mask[i];
            bool valid = mm > 0.5f;
            bool ispos = valid && (g > 0.5f);
            bool cand  = valid && !ispos && (p >= 0.5f);
            if (valid) valc++;
            if (ispos) posc++;
            if (cand) {
                int idx = min((int)(p * 32.0f), 31) - 16;
                sh[(idx >> 2) * BLK + tid] += 1u << ((idx & 3) << 3);
            }
            if (use_scr && (ispos || cand)) {
                unsigned o = atomicAdd(&s_cnt, 1u);
                g_scr[rb + o] = ispos ? -p : p;
            }
        }
    }
    __syncthreads();

    {
        const int b     = tid & 15;
        const int chunk = tid >> 4;
        const int w     = (b >> 2) * BLK;
        const int shft  = (b & 3) << 3;
        unsigned s = 0;
#pragma unroll
        for (int jj = 0; jj < 16; jj++) {
            int j = chunk * 16 + ((jj + b) & 15);
            s += (sh[w + j] >> shft) & 0xFFu;
        }
        if (s) atomicAdd(&s_binsum[b], s);
    }

#pragma unroll
    for (int o = 16; o > 0; o >>= 1) {
        posc += __shfl_down_sync(0xffffffffu, posc, o);
        valc += __shfl_down_sync(0xffffffffu, valc, o);
    }
    if (lane == 0) { w_pc[tid >> 5] = posc; w_vc[tid >> 5] = valc; }
    __syncthreads();

    if (tid < NB1 && s_binsum[tid]) atomicAdd(&g_h1[tid], s_binsum[tid]);
    if (tid == 0) {
        unsigned pc = 0, vc = 0;
#pragma unroll
        for (int w = 0; w < BLK / 32; w++) { pc += w_pc[w]; vc += w_vc[w]; }
        if (pc) atomicAdd(&g_pos_cnt, pc);
        if (vc - pc) atomicAdd(&g_neg_cnt, vc - pc);
        g_cnt_blk[blockIdx.x] = s_cnt;
    }
}

// ---------------------------------------------------------------------------
// K2: merged log-sum over scratch + cheap (count,Σp) sub-bins + finalize
// ---------------------------------------------------------------------------
__global__ void __launch_bounds__(BLK) k2_sums(
    const float4* __restrict__ pred4, const float4* __restrict__ gt4,
    const float4* __restrict__ mask4,
    const float* __restrict__ pred, const float* __restrict__ gt,
    const float* __restrict__ mask, int n, int cap, int use_scr,
    float* __restrict__ out)
{
    __shared__ unsigned int s_h1[NB1];
    __shared__ int          s_T1;
    __shared__ unsigned int s_c2[NB2];
    __shared__ float        s_s2[NB2];     // Σp
    __shared__ unsigned int s_fc[NFB];
    __shared__ float        s_fs[NFB];     // Σp
    __shared__ float        w_es[BLK / 32];
    __shared__ unsigned int s_isLast;

    const int tid = threadIdx.x;
    if (tid < NB1) s_h1[tid] = g_h1[tid];
    if (tid < NB2) { s_c2[tid] = 0u; s_s2[tid] = 0.0f; }
    __syncthreads();

    if (tid == 0) {
        long long k;
        s_T1 = find_T1(s_h1, g_pos_cnt, (long long)g_neg_cnt, k);
    }
    __syncthreads();
    const int T1 = s_T1;

    float mA = 1.0f, mB = 1.0f;   // two ILP accumulators
    int   eA = 0,    eB = 0;
    float esum = 0.0f;
    bool wrote_fine = false;

    // hot-path handler: NO log anywhere; rare branch is ~7 instructions.
    auto pv = [&](float v, float& m, int& e) {
        bool isPos = v < 0.0f;
        float x = isPos ? -v : 1.0f - v;
        int b = min((int)(v * 32.0f), 31);
        if (!isPos && b == T1) {               // cheap: count + Σp only
            int b2 = (int)(v * 2048.0f) - T1 * 64;
            b2 = max(0, min(b2, NB2 - 1));
            atomicAdd(&s_c2[b2], 1u);
            atomicAdd(&s_s2[b2], v);
        }
        bool take = isPos || (b > T1);
        float xm = take ? x : 1.0f;
        if (xm < 1e-37f) { esum += 100.0f; xm = 1.0f; }   // never in-range; exact clamp
        m *= xm;
        int i = __float_as_int(m);
        e += ((i >> 23) & 0xFF) - 127;
        m = __int_as_float((i & 0x807FFFFFu) | 0x3F800000u);
    };

    if (use_scr && T1 >= 16) {
        const long long rb  = (long long)blockIdx.x * (long long)cap;
        const unsigned  cnt = g_cnt_blk[blockIdx.x];
        const float4*   s4  = (const float4*)&g_scr[rb];
        const unsigned  c4  = cnt >> 2;
        unsigned j = tid;
        for (; j + 3u * BLK < c4; j += 4u * BLK) {       // MLP-4
            float4 a  = s4[j];
            float4 b4 = s4[j + BLK];
            float4 c  = s4[j + 2u * BLK];
            float4 d  = s4[j + 3u * BLK];
            pv(a.x,  mA, eA); pv(a.y,  mB, eB); pv(a.z,  mA, eA); pv(a.w,  mB, eB);
            pv(b4.x, mA, eA); pv(b4.y, mB, eB); pv(b4.z, mA, eA); pv(b4.w, mB, eB);
            pv(c.x,  mA, eA); pv(c.y,  mB, eB); pv(c.z,  mA, eA); pv(c.w,  mB, eB);
            pv(d.x,  mA, eA); pv(d.y,  mB, eB); pv(d.z,  mA, eA); pv(d.w,  mB, eB);
        }
        for (; j < c4; j += BLK) {
            float4 a = s4[j];
            pv(a.x, mA, eA); pv(a.y, mB, eB); pv(a.z, mA, eA); pv(a.w, mB, eB);
        }
        for (unsigned t = (c4 << 2) + tid; t < cnt; t += BLK) pv(g_scr[rb + t], mA, eA);
    } else {
        // cold path: full re-read
        wrote_fine = (T1 == -1);
        for (int i = tid; i < NFB; i += BLK) { s_fc[i] = 0u; s_fs[i] = 0.0f; }
        __syncthreads();
        const int n4 = n >> 2;
        const int stp = gridDim.x * BLK;
        auto hfull = [&](float p, float g, float mm) {
            if (mm > 0.5f) {
                if (g > 0.5f) { esum += pos_loss_f(p); return; }
                if (T1 == 1000) return;
                if (T1 >= 16) {
                    int b = min((int)(p * 32.0f), 31);
                    if (b > T1) esum += neg_loss_f(p);
                    else if (b == T1) {
                        int b2 = (int)(p * 2048.0f) - T1 * 64;
                        b2 = max(0, min(b2, NB2 - 1));
                        atomicAdd(&s_c2[b2], 1u);
                        atomicAdd(&s_s2[b2], p);
                    }
                } else {
                    if (p >= 0.5f) esum += neg_loss_f(p);
                    else {
                        int fb = max(0, min((int)(p * 2048.0f), NFB - 1));
                        atomicAdd(&s_fc[fb], 1u);
                        atomicAdd(&s_fs[fb], p);
                    }
                }
            }
        };
        for (int ib = blockIdx.x * BLK; ib < n4; ib += stp) {
            int i = ib + tid;
            if (i < n4) {
                float4 p = pred4[i], g = gt4[i], m = mask4[i];
                hfull(p.x, g.x, m.x); hfull(p.y, g.y, m.y);
                hfull(p.z, g.z, m.z); hfull(p.w, g.w, m.w);
            }
        }
        if (blockIdx.x == 0) {
            for (int i = (n4 << 2) + tid; i < n; i += BLK)
                hfull(pred[i], gt[i], mask[i]);
        }
        __syncthreads();
        if (wrote_fine) {
            for (int i = tid; i < NFB; i += BLK) {
                if (s_fc[i]) { atomicAdd(&g_fc[i], s_fc[i]); atomicAdd(&g_fs[i], s_fs[i]); }
            }
        }
    }

    esum += finish_log(mA, eA) + finish_log(mB, eB);

#pragma unroll
    for (int o = 16; o > 0; o >>= 1)
        esum += __shfl_down_sync(0xffffffffu, esum, o);
    if ((tid & 31) == 0) w_es[tid >> 5] = esum;
    __syncthreads();

    if (tid < NB2 && s_c2[tid]) {
        atomicAdd(&g_h2c[tid], s_c2[tid]);
        atomicAdd(&g_h2s[tid], s_s2[tid]);
    }
    if (tid == 0) {
        float es = 0.0f;
#pragma unroll
        for (int w = 0; w < BLK / 32; w++) es += w_es[w];
        atomicAdd(&g_sum_main, (double)es);
    }

    // ---- last-block finalize ----------------------------------------------
    __threadfence();
    __syncthreads();
    if (tid == 0) {
        unsigned old = atomicAdd(&g_done, 1u);
        s_isLast = (old == gridDim.x - 1u) ? 1u : 0u;
    }
    __syncthreads();
    if (!s_isLast) return;

    if (tid < NB2) { s_c2[tid] = g_h2c[tid]; s_s2[tid] = g_h2s[tid]; }
    if (T1 == -1) {
        for (int i = tid; i < NFB; i += BLK) { s_fc[i] = g_fc[i]; s_fs[i] = g_fs[i]; }
    }
    __syncthreads();

    if (tid == 0) {
        unsigned pos = g_pos_cnt;
        long long k;
        int T1f = find_T1(s_h1, pos, (long long)g_neg_cnt, k);

        // per-bin loss sum from (count, Σp):  cnt * (-log(1 - mean_p))
        auto binloss = [](unsigned c, float sp) -> double {
            if (c == 0u) return 0.0;
            float mean = sp / (float)c;
            return (double)c * (double)fminf(-fast_log(1.0f - mean), 100.0f);
        };

        double extra = 0.0;
        if (k > 0) {
            if (T1f >= 16 && T1f < 32) {
                long long cAbove1 = 0;
                for (int i = T1f + 1 - 16; i < NB1; i++) cAbove1 += (long long)s_h1[i];
                long long r = k - cAbove1;

                long long c2 = 0, cAbove2 = 0;
                double s2above = 0.0;
                int T2 = -1;
                for (int i = NB2 - 1; i >= 0; i--) {
                    long long cn = c2 + (long long)s_c2[i];
                    if (cn >= r) { T2 = i; cAbove2 = c2; break; }
                    s2above += binloss(s_c2[i], s_s2[i]);
                    c2 = cn;
                }
                double part = 0.0;
                if (T2 >= 0 && s_c2[T2] > 0u) {
                    long long r2 = r - cAbove2;
                    if (r2 < 0) r2 = 0;
                    part = binloss(s_c2[T2], s_s2[T2]) *
                           ((double)r2 / (double)s_c2[T2]);
                }
                extra = s2above + part;
            } else if (T1f == -1) {
                long long cand = 0;
                for (int i = 0; i < NB1; i++) cand += (long long)s_h1[i];
                long long r = k - cand;
                long long c2 = 0, cAbove2 = 0;
                double s2above = 0.0;
                int T2 = -1;
                for (int i = NFB - 1; i >= 0; i--) {
                    long long cn = c2 + (long long)s_fc[i];
                    if (cn >= r) { T2 = i; cAbove2 = c2; break; }
                    s2above += binloss(s_fc[i], s_fs[i]);
                    c2 = cn;
                }
                double part = 0.0;
                if (T2 >= 0 && s_fc[T2] > 0u) {
                    long long r2 = r - cAbove2;
                    if (r2 < 0) r2 = 0;
                    part = binloss(s_fc[T2], s_fs[T2]) *
                           ((double)r2 / (double)s_fc[T2]);
                }
                extra = s2above + part;
            }
        }

        double denom = (double)pos + (double)k + 1e-6;
        out[0] = (float)((g_sum_main + extra) / denom);
    }
    __syncthreads();

    // reset globals for graph replay
    if (tid < NB1) g_h1[tid] = 0u;
    if (tid < NB2) { g_h2c[tid] = 0u; g_h2s[tid] = 0.0f; }
    for (int i = tid; i < NFB; i += BLK) { g_fc[i] = 0u; g_fs[i] = 0.0f; }
    if (tid == 0) {
        g_pos_cnt  = 0u;
        g_neg_cnt  = 0u;
        g_sum_main = 0.0;
        g_done     = 0u;
    }
}

// ---------------------------------------------------------------------------
extern "C" void kernel_launch(void* const* d_in, const int* in_sizes, int n_in,
                              void* d_out, int out_size)
{
    const float* pred = (const float*)d_in[0];
    const float* gt   = (const float*)d_in[1];
    const float* mask = (const float*)d_in[2];
    float* out = (float*)d_out;
    const int n = in_sizes[0];

    const float4* pred4 = (const float4*)pred;
    const float4* gt4   = (const float4*)gt;
    const float4* mask4 = (const float4*)mask;

    int n4 = n >> 2;
    int grid = (n4 + BLK - 1) / BLK;
    if (grid > GRID_CAP) grid = GRID_CAP;
    if (grid < 1) grid = 1;

    int iters = (n4 + grid * BLK - 1) / (grid * BLK);
    long long cap = (long long)iters * BLK * 4 + 8;
    int use_scr = ((long long)grid * cap <= (long long)SCR_SZ) ? 1 : 0;

    k1_scan<<<grid, BLK>>>(pred4, gt4, mask4, pred, gt, mask, n, (int)cap, use_scr);
    k2_sums<<<grid, BLK>>>(pred4, gt4, mask4, pred, gt, mask, n, (int)cap, use_scr, out);
}

// round 10
// speedup vs baseline: 1.2059x; 1.0860x over previous
#include <cuda_runtime.h>

// ---------------------------------------------------------------------------
// MaskedBalancedBCELoss — 2-kernel pipeline.
//  K1 (one 157 MB streaming read): counts pos/valid in regs; u8-packed 16-bin
//     histogram of p over CANDIDATES (negatives with p>=0.5); ballot-compacts
//     tagged candidates (negatives +p, positives -p) into per-block scratch.
//  K2: threshold bin T1 -> one pass over scratch with a merged log-sum
//      (mantissa-product + exponent, 2-way ILP, float-compare bin tests).
//      Bin == T1 -> COUNT-only sub-bin shared atomics; finalize reconstructs
//      sub-bin loss sums from counts x midpoint loss. Cold fallback: full
//      re-read with 1024 fine count bins. LAST block (fence+counter)
//      finalizes and resets globals (graph-replay safe).
// ---------------------------------------------------------------------------

#define NB1 16             // bins 16..31 of (int)(p*32)
#define NB2 64
#define NFB 1024           // fine bins over [0,0.5) for the cold fallback
#define BLK 256
#define GRID_CAP 888
#define SCR_SZ (16u << 20) // 16M floats = 64 MB

__device__ __align__(16) float g_scr[SCR_SZ];
__device__ unsigned int g_cnt_blk[GRID_CAP];
__device__ unsigned int g_h1[NB1];
__device__ unsigned int g_h2c[NB2];
__device__ unsigned int g_fc[NFB];
__device__ unsigned int g_pos_cnt;
__device__ unsigned int g_neg_cnt;
__device__ double       g_sum_main;   // positives + above-threshold negatives
__device__ unsigned int g_done;

// Cephes-style natural log, pure FMA/ALU (no MUFU). ~1-2 ulp on normals.
__device__ __forceinline__ float fast_log(float x) {
    int   i  = __float_as_int(x);
    int   e  = ((i >> 23) & 0xFF) - 127;
    float m  = __int_as_float((i & 0x007FFFFF) | 0x3F800000);
    if (m > 1.41421356f) { m *= 0.5f; e += 1; }
    float t  = m - 1.0f;
    float z  = t * t;
    float P  = 7.0376836292e-2f;
    P = P * t - 1.1514610310e-1f;
    P = P * t + 1.1676998740e-1f;
    P = P * t - 1.2420140846e-1f;
    P = P * t + 1.4249322787e-1f;
    P = P * t - 1.6668057665e-1f;
    P = P * t + 2.0000714765e-1f;
    P = P * t - 2.4999993993e-1f;
    P = P * t + 3.3333331174e-1f;
    float fe = (float)e;
    float y  = t * z * P;
    y += fe * -2.12194440e-4f;
    y -= 0.5f * z;
    float r  = t + y;
    r += fe * 0.693359375f;
    return r;
}
__device__ __forceinline__ float pos_loss_f(float p) { return fminf(-fast_log(p), 100.0f); }
__device__ __forceinline__ float neg_loss_f(float p) { return fminf(-fast_log(1.0f - p), 100.0f); }

// Threshold bin. 1000 if k==0; -1 if below bin 16 (cold); else T1 in [16,31].
__device__ __forceinline__ int find_T1(const unsigned* h1, unsigned pos,
                                       long long negtot, long long& k_out) {
    long long k3p = 3LL * (long long)pos;
    long long k = (pos == 0u) ? 0LL : (negtot < k3p ? negtot : k3p);
    k_out = k;
    if (k == 0) return 1000;
    long long c = 0;
    for (int i = NB1 - 1; i >= 0; i--) {
        c += (long long)h1[i];
        if (c >= k) return i + 16;
    }
    return -1;
}

// ---------------------------------------------------------------------------
// K1: stream, classify, candidate histogram, compact.  (unchanged)
// ---------------------------------------------------------------------------
__global__ void __launch_bounds__(BLK, 6) k1_scan(
    const float4* __restrict__ pred4, const float4* __restrict__ gt4,
    const float4* __restrict__ mask4,
    const float* __restrict__ pred, const float* __restrict__ gt,
    const float* __restrict__ mask, int n, int cap, int use_scr)
{
    __shared__ unsigned int sh[4 * BLK];
    __shared__ unsigned int s_binsum[NB1];
    __shared__ unsigned int s_cnt;
    __shared__ unsigned int w_pc[BLK / 32], w_vc[BLK / 32];

    const int tid  = threadIdx.x;
    const int lane = tid & 31;
    const unsigned lt = (1u << lane) - 1u;

#pragma unroll
    for (int w = 0; w < 4; w++) sh[w * BLK + tid] = 0u;
    if (tid < NB1) s_binsum[tid] = 0u;
    if (tid == 0) s_cnt = 0u;
    __syncthreads();

    unsigned int posc = 0, valc = 0;
    const int n4   = n >> 2;
    const int step = gridDim.x * BLK;
    const long long rb = (long long)blockIdx.x * (long long)cap;

    auto procE = [&](float p, float g, float mm, bool in, float& v) -> bool {
        bool valid = in && (mm > 0.5f);
        bool ispos = valid && (g > 0.5f);
        valc += valid ? 1u : 0u;
        posc += ispos ? 1u : 0u;
        v = ispos ? -p : p;
        bool cand = valid && !(g > 0.5f) && (p >= 0.5f);
        if (cand) {
            int idx = min((int)(p * 32.0f), 31) - 16;
            sh[(idx >> 2) * BLK + tid] += 1u << ((idx & 3) << 3);
        }
        return ispos || cand;
    };

    int ibase = blockIdx.x * BLK;
    while (ibase + step + BLK <= n4) {
        int i0 = ibase + tid, i1 = i0 + step;
        float4 pa = __ldcs(&pred4[i0]), ga = __ldcs(&gt4[i0]), ma = __ldcs(&mask4[i0]);
        float4 pb = __ldcs(&pred4[i1]), gb = __ldcs(&gt4[i1]), mb = __ldcs(&mask4[i1]);
        float v0, v1, v2, v3, v4, v5, v6, v7;
        bool c0 = procE(pa.x, ga.x, ma.x, true, v0);
        bool c1 = procE(pa.y, ga.y, ma.y, true, v1);
        bool c2 = procE(pa.z, ga.z, ma.z, true, v2);
        bool c3 = procE(pa.w, ga.w, ma.w, true, v3);
        bool c4 = procE(pb.x, gb.x, mb.x, true, v4);
        bool c5 = procE(pb.y, gb.y, mb.y, true, v5);
        bool c6 = procE(pb.z, gb.z, mb.z, true, v6);
        bool c7 = procE(pb.w, gb.w, mb.w, true, v7);
        if (use_scr) {
            unsigned m0 = __ballot_sync(0xffffffffu, c0);
            unsigned m1 = __ballot_sync(0xffffffffu, c1);
            unsigned m2 = __ballot_sync(0xffffffffu, c2);
            unsigned m3 = __ballot_sync(0xffffffffu, c3);
            unsigned m4 = __ballot_sync(0xffffffffu, c4);
            unsigned m5 = __ballot_sync(0xffffffffu, c5);
            unsigned m6 = __ballot_sync(0xffffffffu, c6);
            unsigned m7 = __ballot_sync(0xffffffffu, c7);
            unsigned tot = __popc(m0) + __popc(m1) + __popc(m2) + __popc(m3)
                         + __popc(m4) + __popc(m5) + __popc(m6) + __popc(m7);
            unsigned base = 0;
            if (lane == 0 && tot) base = atomicAdd(&s_cnt, tot);
            base = __shfl_sync(0xffffffffu, base, 0);
            unsigned s = base;
            if (c0) g_scr[rb + s + __popc(m0 & lt)] = v0; s += __popc(m0);
            if (c1) g_scr[rb + s + __popc(m1 & lt)] = v1; s += __popc(m1);
            if (c2) g_scr[rb + s + __popc(m2 & lt)] = v2; s += __popc(m2);
            if (c3) g_scr[rb + s + __popc(m3 & lt)] = v3; s += __popc(m3);
            if (c4) g_scr[rb + s + __popc(m4 & lt)] = v4; s += __popc(m4);
            if (c5) g_scr[rb + s + __popc(m5 & lt)] = v5; s += __popc(m5);
            if (c6) g_scr[rb + s + __popc(m6 & lt)] = v6; s += __popc(m6);
            if (c7) g_scr[rb + s + __popc(m7 & lt)] = v7;
        }
        ibase += 2 * step;
    }
    for (; ibase < n4; ibase += step) {
        int i = ibase + tid;
        bool in = i < n4;
        float4 pa = in ? __ldcs(&pred4[i]) : make_float4(0.f, 0.f, 0.f, 0.f);
        float4 ga = in ? __ldcs(&gt4[i])   : make_float4(1.f, 1.f, 1.f, 1.f);
        float4 ma = in ? __ldcs(&mask4[i]) : make_float4(0.f, 0.f, 0.f, 0.f);
        float v0, v1, v2, v3;
        bool c0 = procE(pa.x, ga.x, ma.x, in, v0);
        bool c1 = procE(pa.y, ga.y, ma.y, in, v1);
        bool c2 = procE(pa.z, ga.z, ma.z, in, v2);
        bool c3 = procE(pa.w, ga.w, ma.w, in, v3);
        if (use_scr) {
            unsigned m0 = __ballot_sync(0xffffffffu, c0);
            unsigned m1 = __ballot_sync(0xffffffffu, c1);
            unsigned m2 = __ballot_sync(0xffffffffu, c2);
            unsigned m3 = __ballot_sync(0xffffffffu, c3);
            unsigned tot = __popc(m0) + __popc(m1) + __popc(m2) + __popc(m3);
            unsigned base = 0;
            if (lane == 0 && tot) base = atomicAdd(&s_cnt, tot);
            base = __shfl_sync(0xffffffffu, base, 0);
            unsigned s = base;
            if (c0) g_scr[rb + s + __popc(m0 & lt)] = v0; s += __popc(m0);
            if (c1) g_scr[rb + s + __popc(m1 & lt)] = v1; s += __popc(m1);
            if (c2) g_scr[rb + s + __popc(m2 & lt)] = v2; s += __popc(m2);
            if (c3) g_scr[rb + s + __popc(m3 & lt)] = v3;
        }
    }
    if (blockIdx.x == 0) {
        for (int i = (n4 << 2) + tid; i < n; i += BLK) {
            float p = pred[i], g = gt[i], mm = mask[i];
            bool valid = mm > 0.5f;
            bool ispos = valid && (g > 0.5f);
            bool cand  = valid && !ispos && (p >= 0.5f);
            if (valid) valc++;
            if (ispos) posc++;
            if (cand) {
                int idx = min((int)(p * 32.0f), 31) - 16;
                sh[(idx >> 2) * BLK + tid] += 1u << ((idx & 3) << 3);
            }
            if (use_scr && (ispos || cand)) {
                unsigned o = atomicAdd(&s_cnt, 1u);
                g_scr[rb + o] = ispos ? -p : p;
            }
        }
    }
    __syncthreads();

    {
        const int b     = tid & 15;
        const int chunk = tid >> 4;
        const int w     = (b >> 2) * BLK;
        const int shft  = (b & 3) << 3;
        unsigned s = 0;
#pragma unroll
        for (int jj = 0; jj < 16; jj++) {
            int j = chunk * 16 + ((jj + b) & 15);
            s += (sh[w + j] >> shft) & 0xFFu;
        }
        if (s) atomicAdd(&s_binsum[b], s);
    }

#pragma unroll
    for (int o = 16; o > 0; o >>= 1) {
        posc += __shfl_down_sync(0xffffffffu, posc, o);
        valc += __shfl_down_sync(0xffffffffu, valc, o);
    }
    if (lane == 0) { w_pc[tid >> 5] = posc; w_vc[tid >> 5] = valc; }
    __syncthreads();

    if (tid < NB1 && s_binsum[tid]) atomicAdd(&g_h1[tid], s_binsum[tid]);
    if (tid == 0) {
        unsigned pc = 0, vc = 0;
#pragma unroll
        for (int w = 0; w < BLK / 32; w++) { pc += w_pc[w]; vc += w_vc[w]; }
        if (pc) atomicAdd(&g_pos_cnt, pc);
        if (vc - pc) atomicAdd(&g_neg_cnt, vc - pc);
        g_cnt_blk[blockIdx.x] = s_cnt;
    }
}

// ---------------------------------------------------------------------------
// K2: lean merged log-sum + count-only sub-bins + last-block finalize
// ---------------------------------------------------------------------------
__global__ void __launch_bounds__(BLK) k2_sums(
    const float4* __restrict__ pred4, const float4* __restrict__ gt4,
    const float4* __restrict__ mask4,
    const float* __restrict__ pred, const float* __restrict__ gt,
    const float* __restrict__ mask, int n, int cap, int use_scr,
    float* __restrict__ out)
{
    __shared__ unsigned int s_h1[NB1];
    __shared__ int          s_T1;
    __shared__ unsigned int s_c2[NB2];
    __shared__ unsigned int s_fc[NFB];
    __shared__ float        w_es[BLK / 32];
    __shared__ unsigned int s_isLast;

    const int tid = threadIdx.x;
    if (tid < NB1) s_h1[tid] = g_h1[tid];
    if (tid < NB2) s_c2[tid] = 0u;
    __syncthreads();

    if (tid == 0) {
        long long k;
        s_T1 = find_T1(s_h1, g_pos_cnt, (long long)g_neg_cnt, k);
    }
    __syncthreads();
    const int T1 = s_T1;

    // float-compare bounds (T1==1000 -> lo/hi huge: inT1 false, take=isPos)
    const float lo = (T1 < 32) ? (float)T1 * 0.03125f : 1e30f;
    const float hi = (T1 < 32) ? lo + 0.03125f        : 2e30f;
    const int   t1x64 = (T1 < 32) ? T1 * 64 : 0;

    float mA = 1.0f, mB = 1.0f;   // two ILP mantissa products
    int   e = 0;                  // shared exponent accumulator (bias-free)
    float esum = 0.0f;

    // lean per-element handler
    auto pv = [&](float v, float& m) {
        bool isPos = v < 0.0f;
        float x = isPos ? -v : 1.0f - v;
        x = fmaxf(x, 2e-38f);                 // keep normal (loss cap ~86.9)
        if (v >= lo && v < hi) {              // bin == T1 (positives excluded: v<0)
            int b2 = min((int)(v * 2048.0f) - t1x64, NB2 - 1);
            b2 = max(b2, 0);
            atomicAdd(&s_c2[b2], 1u);
        }
        bool take = isPos || (v >= hi);
        m *= take ? x : 1.0f;
        int i = __float_as_int(m);            // m > 0 always
        e += (i >> 23) - 127;
        m = __int_as_float((i & 0x007FFFFF) | 0x3F800000);
    };

    bool wrote_fine = false;

    if (use_scr && T1 >= 16) {
        const long long rb  = (long long)blockIdx.x * (long long)cap;
        const unsigned  cnt = g_cnt_blk[blockIdx.x];
        const float4*   s4  = (const float4*)&g_scr[rb];
        const unsigned  c4  = cnt >> 2;
        unsigned j = tid;
        for (; j + 3u * BLK < c4; j += 4u * BLK) {       // MLP-4
            float4 a  = s4[j];
            float4 b4 = s4[j + BLK];
            float4 c  = s4[j + 2u * BLK];
            float4 d  = s4[j + 3u * BLK];
            pv(a.x,  mA); pv(a.y,  mB); pv(a.z,  mA); pv(a.w,  mB);
            pv(b4.x, mA); pv(b4.y, mB); pv(b4.z, mA); pv(b4.w, mB);
            pv(c.x,  mA); pv(c.y,  mB); pv(c.z,  mA); pv(c.w,  mB);
            pv(d.x,  mA); pv(d.y,  mB); pv(d.z,  mA); pv(d.w,  mB);
        }
        for (; j < c4; j += BLK) {
            float4 a = s4[j];
            pv(a.x, mA); pv(a.y, mB); pv(a.z, mA); pv(a.w, mB);
        }
        for (unsigned t = (c4 << 2) + tid; t < cnt; t += BLK) pv(g_scr[rb + t], mA);
    } else {
        // cold path: full re-read
        wrote_fine = (T1 == -1);
        for (int i = tid; i < NFB; i += BLK) s_fc[i] = 0u;
        __syncthreads();
        const int n4 = n >> 2;
        const int stp = gridDim.x * BLK;
        auto hfull = [&](float p, float g, float mm) {
            if (mm > 0.5f) {
                if (g > 0.5f) { esum += pos_loss_f(p); return; }
                if (T1 == 1000) return;
                if (T1 >= 16) {
                    int b = min((int)(p * 32.0f), 31);
                    if (b > T1) esum += neg_loss_f(p);
                    else if (b == T1) {
                        int b2 = (int)(p * 2048.0f) - t1x64;
                        b2 = max(0, min(b2, NB2 - 1));
                        atomicAdd(&s_c2[b2], 1u);
                    }
                } else {
                    if (p >= 0.5f) esum += neg_loss_f(p);
                    else {
                        int fb = max(0, min((int)(p * 2048.0f), NFB - 1));
                        atomicAdd(&s_fc[fb], 1u);
                    }
                }
            }
        };
        for (int ib = blockIdx.x * BLK; ib < n4; ib += stp) {
            int i = ib + tid;
            if (i < n4) {
                float4 p = pred4[i], g = gt4[i], m = mask4[i];
                hfull(p.x, g.x, m.x); hfull(p.y, g.y, m.y);
                hfull(p.z, g.z, m.z); hfull(p.w, g.w, m.w);
            }
        }
        if (blockIdx.x == 0) {
            for (int i = (n4 << 2) + tid; i < n; i += BLK)
                hfull(pred[i], gt[i], mask[i]);
        }
        __syncthreads();
        if (wrote_fine) {
            for (int i = tid; i < NFB; i += BLK)
                if (s_fc[i]) atomicAdd(&g_fc[i], s_fc[i]);
        }
    }

    esum += -(fast_log(mA) + fast_log(mB) + (float)e * 0.69314718056f);

#pragma unroll
    for (int o = 16; o > 0; o >>= 1)
        esum += __shfl_down_sync(0xffffffffu, esum, o);
    if ((tid & 31) == 0) w_es[tid >> 5] = esum;
    __syncthreads();

    if (tid < NB2 && s_c2[tid]) atomicAdd(&g_h2c[tid], s_c2[tid]);
    if (tid == 0) {
        float es = 0.0f;
#pragma unroll
        for (int w = 0; w < BLK / 32; w++) es += w_es[w];
        atomicAdd(&g_sum_main, (double)es);
    }

    // ---- last-block finalize ----------------------------------------------
    __threadfence();
    __syncthreads();
    if (tid == 0) {
        unsigned old = atomicAdd(&g_done, 1u);
        s_isLast = (old == gridDim.x - 1u) ? 1u : 0u;
    }
    __syncthreads();
    if (!s_isLast) return;

    if (tid < NB2) s_c2[tid] = g_h2c[tid];
    if (T1 == -1) {
        for (int i = tid; i < NFB; i += BLK) s_fc[i] = g_fc[i];
    }
    __syncthreads();

    if (tid == 0) {
        unsigned pos = g_pos_cnt;
        long long k;
        int T1f = find_T1(s_h1, pos, (long long)g_neg_cnt, k);

        double extra = 0.0;
        if (k > 0) {
            if (T1f >= 16 && T1f < 32) {
                // loss of sub-bin i (midpoint): -log(1 - p_mid)
                auto subloss = [&](int i) -> double {
                    float pm = ((float)(T1f * 64 + i) + 0.5f) * (1.0f / 2048.0f);
                    return (double)fminf(-fast_log(1.0f - pm), 100.0f);
                };
                long long cAbove1 = 0;
                for (int i = T1f + 1 - 16; i < NB1; i++) cAbove1 += (long long)s_h1[i];
                long long r = k - cAbove1;

                long long c2 = 0, cAbove2 = 0;
                double s2above = 0.0;
                int T2 = -1;
                for (int i = NB2 - 1; i >= 0; i--) {
                    long long cn = c2 + (long long)s_c2[i];
                    if (cn >= r) { T2 = i; cAbove2 = c2; break; }
                    s2above += (double)s_c2[i] * subloss(i);
                    c2 = cn;
                }
                double part = 0.0;
                if (T2 >= 0 && s_c2[T2] > 0u) {
                    long long r2 = r - cAbove2;
                    if (r2 < 0) r2 = 0;
                    part = (double)r2 * subloss(T2);
                }
                extra = s2above + part;
            } else if (T1f == -1) {
                auto fineloss = [&](int i) -> double {
                    float pm = ((float)i + 0.5f) * (1.0f / 2048.0f);
                    return (double)fminf(-fast_log(1.0f - pm), 100.0f);
                };
                long long cand = 0;
                for (int i = 0; i < NB1; i++) cand += (long long)s_h1[i];
                long long r = k - cand;
                long long c2 = 0, cAbove2 = 0;
                double s2above = 0.0;
                int T2 = -1;
                for (int i = NFB - 1; i >= 0; i--) {
                    long long cn = c2 + (long long)s_fc[i];
                    if (cn >= r) { T2 = i; cAbove2 = c2; break; }
                    s2above += (double)s_fc[i] * fineloss(i);
                    c2 = cn;
                }
                double part = 0.0;
                if (T2 >= 0 && s_fc[T2] > 0u) {
                    long long r2 = r - cAbove2;
                    if (r2 < 0) r2 = 0;
                    part = (double)r2 * fineloss(T2);
                }
                extra = s2above + part;
            }
        }

        double denom = (double)pos + (double)k + 1e-6;
        out[0] = (float)((g_sum_main + extra) / denom);
    }
    __syncthreads();

    // reset globals for graph replay
    if (tid < NB1) g_h1[tid] = 0u;
    if (tid < NB2) g_h2c[tid] = 0u;
    for (int i = tid; i < NFB; i += BLK) g_fc[i] = 0u;
    if (tid == 0) {
        g_pos_cnt  = 0u;
        g_neg_cnt  = 0u;
        g_sum_main = 0.0;
        g_done     = 0u;
    }
}

// ---------------------------------------------------------------------------
extern "C" void kernel_launch(void* const* d_in, const int* in_sizes, int n_in,
                              void* d_out, int out_size)
{
    const float* pred = (const float*)d_in[0];
    const float* gt   = (const float*)d_in[1];
    const float* mask = (const float*)d_in[2];
    float* out = (float*)d_out;
    const int n = in_sizes[0];

    const float4* pred4 = (const float4*)pred;
    const float4* gt4   = (const float4*)gt;
    const float4* mask4 = (const float4*)mask;

    int n4 = n >> 2;
    int grid = (n4 + BLK - 1) / BLK;
    if (grid > GRID_CAP) grid = GRID_CAP;
    if (grid < 1) grid = 1;

    int iters = (n4 + grid * BLK - 1) / (grid * BLK);
    long long cap = (long long)iters * BLK * 4 + 8;
    int use_scr = ((long long)grid * cap <= (long long)SCR_SZ) ? 1 : 0;

    k1_scan<<<grid, BLK>>>(pred4, gt4, mask4, pred, gt, mask, n, (int)cap, use_scr);
    k2_sums<<<grid, BLK>>>(pred4, gt4, mask4, pred, gt, mask, n, (int)cap, use_scr, out);
}

// round 12
// speedup vs baseline: 1.2634x; 1.0477x over previous
#include <cuda_runtime.h>

// ---------------------------------------------------------------------------
// MaskedBalancedBCELoss — 2-kernel pipeline with 16-bit candidate scratch.
//  K1 (one 157 MB streaming read): counts pos/valid in regs; quantizes
//     x = 1-p (neg) / p (pos) to the top-16 rounded float bits (pos tagged by
//     0x8000). Candidacy and the 16-bin histogram are derived from the
//     DEQUANTIZED value, so K2's float-compare classification is bit-exactly
//     consistent with the histogram. Ballot-compacts candidates to u16
//     scratch (~12.5 MB).
//  K2: threshold bin T1 -> one pass over u16 scratch. f = as_float(q<<16) is
//      already the log argument; take-test is ONE compare (f <= xhi; positives
//      have f < 0). Merged log-sum via mantissa-product + exponent. Bin == T1
//      -> count-only sub-bin shared atomics; finalize uses midpoint losses.
//      Cold fallback: full fp32 re-read with 1024 fine count bins. LAST block
//      (fence+counter) finalizes + resets globals (graph-replay safe).
// ---------------------------------------------------------------------------

#define NB1 16               // bins 16..31 of (int)(p'*32), quantized domain
#define NB2 64
#define NFB 1024             // fine bins over [0,0.5) for the cold fallback
#define BLK 256
#define GRID_CAP 888
#define SCR_ELT (32u << 20)  // 32M u16 elements = 64 MB

__device__ __align__(16) unsigned short g_scr16[SCR_ELT];
__device__ unsigned int g_cnt_blk[GRID_CAP];
__device__ unsigned int g_h1[NB1];
__device__ unsigned int g_h2c[NB2];
__device__ unsigned int g_fc[NFB];
__device__ unsigned int g_pos_cnt;
__device__ unsigned int g_neg_cnt;
__device__ double       g_sum_main;
__device__ unsigned int g_done;

// Cephes-style natural log, pure FMA/ALU (no MUFU). ~1-2 ulp on normals.
__device__ __forceinline__ float fast_log(float x) {
    int   i  = __float_as_int(x);
    int   e  = ((i >> 23) & 0xFF) - 127;
    float m  = __int_as_float((i & 0x007FFFFF) | 0x3F800000);
    if (m > 1.41421356f) { m *= 0.5f; e += 1; }
    float t  = m - 1.0f;
    float z  = t * t;
    float P  = 7.0376836292e-2f;
    P = P * t - 1.1514610310e-1f;
    P = P * t + 1.1676998740e-1f;
    P = P * t - 1.2420140846e-1f;
    P = P * t + 1.4249322787e-1f;
    P = P * t - 1.6668057665e-1f;
    P = P * t + 2.0000714765e-1f;
    P = P * t - 2.4999993993e-1f;
    P = P * t + 3.3333331174e-1f;
    float fe = (float)e;
    float y  = t * z * P;
    y += fe * -2.12194440e-4f;
    y -= 0.5f * z;
    float r  = t + y;
    r += fe * 0.693359375f;
    return r;
}
__device__ __forceinline__ float pos_loss_f(float p) { return fminf(-fast_log(p), 100.0f); }
__device__ __forceinline__ float neg_loss_f(float p) { return fminf(-fast_log(1.0f - p), 100.0f); }

// Threshold bin. 1000 if k==0; -1 if below bin 16 (cold); else T1 in [16,31].
__device__ __forceinline__ int find_T1(const unsigned* h1, unsigned pos,
                                       long long negtot, long long& k_out) {
    long long k3p = 3LL * (long long)pos;
    long long k = (pos == 0u) ? 0LL : (negtot < k3p ? negtot : k3p);
    k_out = k;
    if (k == 0) return 1000;
    long long c = 0;
    for (int i = NB1 - 1; i >= 0; i--) {
        c += (long long)h1[i];
        if (c >= k) return i + 16;
    }
    return -1;
}

// ---------------------------------------------------------------------------
// K1: stream, classify (quantized domain), candidate histogram, compact.
// ---------------------------------------------------------------------------
__global__ void __launch_bounds__(BLK, 6) k1_scan(
    const float4* __restrict__ pred4, const float4* __restrict__ gt4,
    const float4* __restrict__ mask4,
    const float* __restrict__ pred, const float* __restrict__ gt,
    const float* __restrict__ mask, int n, int cap, int use_scr)
{
    __shared__ unsigned int sh[4 * BLK];
    __shared__ unsigned int s_binsum[NB1];
    __shared__ unsigned int s_cnt;
    __shared__ unsigned int w_pc[BLK / 32], w_vc[BLK / 32];

    const int tid  = threadIdx.x;
    const int lane = tid & 31;
    const unsigned lt = (1u << lane) - 1u;

#pragma unroll
    for (int w = 0; w < 4; w++) sh[w * BLK + tid] = 0u;
    if (tid < NB1) s_binsum[tid] = 0u;
    if (tid == 0) s_cnt = 0u;
    __syncthreads();

    unsigned int posc = 0, valc = 0;
    const int n4   = n >> 2;
    const int step = gridDim.x * BLK;
    const long long rb = (long long)blockIdx.x * (long long)cap;

    // Quantize FIRST; candidacy and histogram bin come from the dequantized
    // value so K2's float compares match the histogram bit-exactly.
    auto procE = [&](float p, float g, float mm, bool in, unsigned short& q) -> bool {
        bool valid = in && (mm > 0.5f);
        bool ispos = valid && (g > 0.5f);
        valc += valid ? 1u : 0u;
        posc += ispos ? 1u : 0u;
        float x = ispos ? p : (1.0f - p);
        unsigned qq = (__float_as_uint(x) + 0x8000u) >> 16;  // rounded top-16
        q = (unsigned short)(qq | (ispos ? 0x8000u : 0u));
        float f = __int_as_float((int)(qq << 16));           // quantized x > 0
        bool cand = valid && !ispos && (f <= 0.5f);
        if (cand) {
            int idx = (int)((1.0f - f) * 32.0f) - 16;        // exact; 0..15
            idx = max(0, min(idx, 15));
            sh[(idx >> 2) * BLK + tid] += 1u << ((idx & 3) << 3);
        }
        return ispos || cand;
    };

    int ibase = blockIdx.x * BLK;
    while (ibase + step + BLK <= n4) {
        int i0 = ibase + tid, i1 = i0 + step;
        float4 pa = __ldcs(&pred4[i0]), ga = __ldcs(&gt4[i0]), ma = __ldcs(&mask4[i0]);
        float4 pb = __ldcs(&pred4[i1]), gb = __ldcs(&gt4[i1]), mb = __ldcs(&mask4[i1]);
        unsigned short v0, v1, v2, v3, v4, v5, v6, v7;
        bool c0 = procE(pa.x, ga.x, ma.x, true, v0);
        bool c1 = procE(pa.y, ga.y, ma.y, true, v1);
        bool c2 = procE(pa.z, ga.z, ma.z, true, v2);
        bool c3 = procE(pa.w, ga.w, ma.w, true, v3);
        bool c4 = procE(pb.x, gb.x, mb.x, true, v4);
        bool c5 = procE(pb.y, gb.y, mb.y, true, v5);
        bool c6 = procE(pb.z, gb.z, mb.z, true, v6);
        bool c7 = procE(pb.w, gb.w, mb.w, true, v7);
        if (use_scr) {
            unsigned m0 = __ballot_sync(0xffffffffu, c0);
            unsigned m1 = __ballot_sync(0xffffffffu, c1);
            unsigned m2 = __ballot_sync(0xffffffffu, c2);
            unsigned m3 = __ballot_sync(0xffffffffu, c3);
            unsigned m4 = __ballot_sync(0xffffffffu, c4);
            unsigned m5 = __ballot_sync(0xffffffffu, c5);
            unsigned m6 = __ballot_sync(0xffffffffu, c6);
            unsigned m7 = __ballot_sync(0xffffffffu, c7);
            unsigned tot = __popc(m0) + __popc(m1) + __popc(m2) + __popc(m3)
                         + __popc(m4) + __popc(m5) + __popc(m6) + __popc(m7);
            unsigned base = 0;
            if (lane == 0 && tot) base = atomicAdd(&s_cnt, tot);
            base = __shfl_sync(0xffffffffu, base, 0);
            unsigned s = base;
            if (c0) g_scr16[rb + s + __popc(m0 & lt)] = v0; s += __popc(m0);
            if (c1) g_scr16[rb + s + __popc(m1 & lt)] = v1; s += __popc(m1);
            if (c2) g_scr16[rb + s + __popc(m2 & lt)] = v2; s += __popc(m2);
            if (c3) g_scr16[rb + s + __popc(m3 & lt)] = v3; s += __popc(m3);
            if (c4) g_scr16[rb + s + __popc(m4 & lt)] = v4; s += __popc(m4);
            if (c5) g_scr16[rb + s + __popc(m5 & lt)] = v5; s += __popc(m5);
            if (c6) g_scr16[rb + s + __popc(m6 & lt)] = v6; s += __popc(m6);
            if (c7) g_scr16[rb + s + __popc(m7 & lt)] = v7;
        }
        ibase += 2 * step;
    }
    for (; ibase < n4; ibase += step) {
        int i = ibase + tid;
        bool in = i < n4;
        float4 pa = in ? __ldcs(&pred4[i]) : make_float4(0.f, 0.f, 0.f, 0.f);
        float4 ga = in ? __ldcs(&gt4[i])   : make_float4(1.f, 1.f, 1.f, 1.f);
        float4 ma = in ? __ldcs(&mask4[i]) : make_float4(0.f, 0.f, 0.f, 0.f);
        unsigned short v0, v1, v2, v3;
        bool c0 = procE(pa.x, ga.x, ma.x, in, v0);
        bool c1 = procE(pa.y, ga.y, ma.y, in, v1);
        bool c2 = procE(pa.z, ga.z, ma.z, in, v2);
        bool c3 = procE(pa.w, ga.w, ma.w, in, v3);
        if (use_scr) {
            unsigned m0 = __ballot_sync(0xffffffffu, c0);
            unsigned m1 = __ballot_sync(0xffffffffu, c1);
            unsigned m2 = __ballot_sync(0xffffffffu, c2);
            unsigned m3 = __ballot_sync(0xffffffffu, c3);
            unsigned tot = __popc(m0) + __popc(m1) + __popc(m2) + __popc(m3);
            unsigned base = 0;
            if (lane == 0 && tot) base = atomicAdd(&s_cnt, tot);
            base = __shfl_sync(0xffffffffu, base, 0);
            unsigned s = base;
            if (c0) g_scr16[rb + s + __popc(m0 & lt)] = v0; s += __popc(m0);
            if (c1) g_scr16[rb + s + __popc(m1 & lt)] = v1; s += __popc(m1);
            if (c2) g_scr16[rb + s + __popc(m2 & lt)] = v2; s += __popc(m2);
            if (c3) g_scr16[rb + s + __popc(m3 & lt)] = v3;
        }
    }
    if (blockIdx.x == 0) {
        for (int i = (n4 << 2) + tid; i < n; i += BLK) {
            float p = pred[i], g = gt[i], mm = mask[i];
            bool valid = mm > 0.5f;
            bool ispos = valid && (g > 0.5f);
            if (valid) valc++;
            if (ispos) posc++;
            float x = ispos ? p : (1.0f - p);
            unsigned qq = (__float_as_uint(x) + 0x8000u) >> 16;
            float f = __int_as_float((int)(qq << 16));
            bool cand = valid && !ispos && (f <= 0.5f);
            if (cand) {
                int idx = (int)((1.0f - f) * 32.0f) - 16;
                idx = max(0, min(idx, 15));
                sh[(idx >> 2) * BLK + tid] += 1u << ((idx & 3) << 3);
            }
            if (use_scr && (ispos || cand)) {
                unsigned o = atomicAdd(&s_cnt, 1u);
                g_scr16[rb + o] = (unsigned short)(qq | (ispos ? 0x8000u : 0u));
            }
        }
    }
    __syncthreads();

    {   // staggered conflict-free u8 flush
        const int b     = tid & 15;
        const int chunk = tid >> 4;
        const int w     = (b >> 2) * BLK;
        const int shft  = (b & 3) << 3;
        unsigned s = 0;
#pragma unroll
        for (int jj = 0; jj < 16; jj++) {
            int j = chunk * 16 + ((jj + b) & 15);
            s += (sh[w + j] >> shft) & 0xFFu;
        }
        if (s) atomicAdd(&s_binsum[b], s);
    }

#pragma unroll
    for (int o = 16; o > 0; o >>= 1) {
        posc += __shfl_down_sync(0xffffffffu, posc, o);
        valc += __shfl_down_sync(0xffffffffu, valc, o);
    }
    if (lane == 0) { w_pc[tid >> 5] = posc; w_vc[tid >> 5] = valc; }
    __syncthreads();

    if (tid < NB1 && s_binsum[tid]) atomicAdd(&g_h1[tid], s_binsum[tid]);
    if (tid == 0) {
        unsigned pc = 0, vc = 0;
#pragma unroll
        for (int w = 0; w < BLK / 32; w++) { pc += w_pc[w]; vc += w_vc[w]; }
        if (pc) atomicAdd(&g_pos_cnt, pc);
        if (vc - pc) atomicAdd(&g_neg_cnt, vc - pc);
        g_cnt_blk[blockIdx.x] = s_cnt;
    }
}

// ---------------------------------------------------------------------------
// K2: u16 scratch pass + count-only sub-bins + last-block finalize
// ---------------------------------------------------------------------------
__global__ void __launch_bounds__(BLK) k2_sums(
    const float4* __restrict__ pred4, const float4* __restrict__ gt4,
    const float4* __restrict__ mask4,
    const float* __restrict__ pred, const float* __restrict__ gt,
    const float* __restrict__ mask, int n, int cap, int use_scr,
    float* __restrict__ out)
{
    __shared__ unsigned int s_h1[NB1];
    __shared__ int          s_T1;
    __shared__ unsigned int s_c2[NB2];
    __shared__ unsigned int s_fc[NFB];
    __shared__ float        w_es[BLK / 32];
    __shared__ unsigned int s_isLast;

    const int tid = threadIdx.x;
    if (tid < NB1) s_h1[tid] = g_h1[tid];
    if (tid < NB2) s_c2[tid] = 0u;
    __syncthreads();

    if (tid == 0) {
        long long k;
        s_T1 = find_T1(s_h1, g_pos_cnt, (long long)g_neg_cnt, k);
    }
    __syncthreads();
    const int T1 = s_T1;

    // x-domain thresholds (exact multiples of 1/32, zero low-16 bits).
    // warm: above-T1 <=> f <= xhi; in-T1 <=> xhi < f <= xlo.
    // k==0 (T1==1000): xhi = -0.0 -> take = (f <= -0.0) = positives only.
    const bool warm = (T1 >= 16 && T1 < 32);
    const float xhi = warm ? (1.0f - (float)(T1 + 1) * 0.03125f) : -0.0f;
    const float xlo = warm ? (1.0f - (float)T1 * 0.03125f)       : -0.0f;
    const int   t1x64 = warm ? T1 * 64 : 0;

    float mA = 1.0f, mB = 1.0f;
    int   e = 0;
    float esum = 0.0f;

    // per-element handler: q16 -> f = as_float(q<<16).
    auto pv = [&](unsigned q, float& m) {
        float f = __int_as_float((int)(q << 16));
        if (f > xhi && f <= xlo) {                 // bin == T1 (positives f<0)
            float p2 = 1.0f - f;                   // exact
            int b2 = min((int)(p2 * 2048.0f) - t1x64, NB2 - 1);
            b2 = max(b2, 0);
            atomicAdd(&s_c2[b2], 1u);
        }
        bool take = (f <= xhi);
        float x = fmaxf(fabsf(f), 1.1755e-38f);    // keep normal (cap ~87.3)
        m *= take ? x : 1.0f;
        int i = __float_as_int(m);
        e += (i >> 23) - 127;
        m = __int_as_float((i & 0x007FFFFF) | 0x3F800000);
    };
    auto pw = [&](unsigned w, float& m0, float& m1) {   // 2 elements per u32
        pv(w & 0xFFFFu, m0);
        pv(w >> 16, m1);
    };

    bool wrote_fine = false;

    if (use_scr && T1 >= 16) {
        const long long rb  = (long long)blockIdx.x * (long long)cap;
        const unsigned  cnt = g_cnt_blk[blockIdx.x];
        const uint4*    s8  = (const uint4*)&g_scr16[rb];
        const unsigned  c8  = cnt >> 3;            // 8 elements per uint4
        unsigned j = tid;
        for (; j + BLK < c8; j += 2u * BLK) {      // MLP-2 (16 elements/iter)
            uint4 A = s8[j];
            uint4 B = s8[j + BLK];
            pw(A.x, mA, mB); pw(A.y, mA, mB); pw(A.z, mA, mB); pw(A.w, mA, mB);
            pw(B.x, mA, mB); pw(B.y, mA, mB); pw(B.z, mA, mB); pw(B.w, mA, mB);
        }
        for (; j < c8; j += BLK) {
            uint4 A = s8[j];
            pw(A.x, mA, mB); pw(A.y, mA, mB); pw(A.z, mA, mB); pw(A.w, mA, mB);
        }
        for (unsigned t = (c8 << 3) + tid; t < cnt; t += BLK)
            pv((unsigned)g_scr16[rb + t], mA);
    } else {
        // cold path: full fp32 re-read (quantization-free)
        wrote_fine = (T1 == -1);
        for (int i = tid; i < NFB; i += BLK) s_fc[i] = 0u;
        __syncthreads();
        const int n4 = n >> 2;
        const int stp = gridDim.x * BLK;
        auto hfull = [&](float p, float g, float mm) {
            if (mm > 0.5f) {
                if (g > 0.5f) { esum += pos_loss_f(p); return; }
                if (T1 == 1000) return;
                if (p >= 0.5f) esum += neg_loss_f(p);
                else {
                    int fb = max(0, min((int)(p * 2048.0f), NFB - 1));
                    atomicAdd(&s_fc[fb], 1u);
                }
            }
        };
        for (int ib = blockIdx.x * BLK; ib < n4; ib += stp) {
            int i = ib + tid;
            if (i < n4) {
                float4 p = pred4[i], g = gt4[i], m = mask4[i];
                hfull(p.x, g.x, m.x); hfull(p.y, g.y, m.y);
                hfull(p.z, g.z, m.z); hfull(p.w, g.w, m.w);
            }
        }
        if (blockIdx.x == 0) {
            for (int i = (n4 << 2) + tid; i < n; i += BLK)
                hfull(pred[i], gt[i], mask[i]);
        }
        __syncthreads();
        if (wrote_fine) {
            for (int i = tid; i < NFB; i += BLK)
                if (s_fc[i]) atomicAdd(&g_fc[i], s_fc[i]);
        }
    }

    esum += -(fast_log(mA) + fast_log(mB) + (float)e * 0.69314718056f);

#pragma unroll
    for (int o = 16; o > 0; o >>= 1)
        esum += __shfl_down_sync(0xffffffffu, esum, o);
    if ((tid & 31) == 0) w_es[tid >> 5] = esum;
    __syncthreads();

    if (tid < NB2 && s_c2[tid]) atomicAdd(&g_h2c[tid], s_c2[tid]);
    if (tid == 0) {
        float es = 0.0f;
#pragma unroll
        for (int w = 0; w < BLK / 32; w++) es += w_es[w];
        atomicAdd(&g_sum_main, (double)es);
    }

    // ---- last-block finalize ----------------------------------------------
    __threadfence();
    __syncthreads();
    if (tid == 0) {
        unsigned old = atomicAdd(&g_done, 1u);
        s_isLast = (old == gridDim.x - 1u) ? 1u : 0u;
    }
    __syncthreads();
    if (!s_isLast) return;

    if (tid < NB2) s_c2[tid] = g_h2c[tid];
    if (T1 == -1) {
        for (int i = tid; i < NFB; i += BLK) s_fc[i] = g_fc[i];
    }
    __syncthreads();

    if (tid == 0) {
        unsigned pos = g_pos_cnt;
        long long k;
        int T1f = find_T1(s_h1, pos, (long long)g_neg_cnt, k);

        double extra = 0.0;
        if (k > 0) {
            if (T1f >= 16 && T1f < 32) {
                auto subloss = [&](int i) -> double {
                    float pm = ((float)(T1f * 64 + i) + 0.5f) * (1.0f / 2048.0f);
                    return (double)fminf(-fast_log(1.0f - pm), 100.0f);
                };
                long long cAbove1 = 0;
                for (int i = T1f + 1 - 16; i < NB1; i++) cAbove1 += (long long)s_h1[i];
                long long r = k - cAbove1;

                long long c2 = 0, cAbove2 = 0;
                double s2above = 0.0;
                int T2 = -1;
                for (int i = NB2 - 1; i >= 0; i--) {
                    long long cn = c2 + (long long)s_c2[i];
                    if (cn >= r) { T2 = i; cAbove2 = c2; break; }
                    s2above += (double)s_c2[i] * subloss(i);
                    c2 = cn;
                }
                double part = 0.0;
                if (T2 >= 0 && s_c2[T2] > 0u) {
                    long long r2 = r - cAbove2;
                    if (r2 < 0) r2 = 0;
                    part = (double)r2 * subloss(T2);
                }
                extra = s2above + part;
            } else if (T1f == -1) {
                auto fineloss = [&](int i) -> double {
                    float pm = ((float)i + 0.5f) * (1.0f / 2048.0f);
                    return (double)fminf(-fast_log(1.0f - pm), 100.0f);
                };
                long long cand = 0;
                for (int i = 0; i < NB1; i++) cand += (long long)s_h1[i];
                long long r = k - cand;
                long long c2 = 0, cAbove2 = 0;
                double s2above = 0.0;
                int T2 = -1;
                for (int i = NFB - 1; i >= 0; i--) {
                    long long cn = c2 + (long long)s_fc[i];
                    if (cn >= r) { T2 = i; cAbove2 = c2; break; }
                    s2above += (double)s_fc[i] * fineloss(i);
                    c2 = cn;
                }
                double part = 0.0;
                if (T2 >= 0 && s_fc[T2] > 0u) {
                    long long r2 = r - cAbove2;
                    if (r2 < 0) r2 = 0;
                    part = (double)r2 * fineloss(T2);
                }
                extra = s2above + part;
            }
        }

        double denom = (double)pos + (double)k + 1e-6;
        out[0] = (float)((g_sum_main + extra) / denom);
    }
    __syncthreads();

    // reset globals for graph replay
    if (tid < NB1) g_h1[tid] = 0u;
    if (tid < NB2) g_h2c[tid] = 0u;
    for (int i = tid; i < NFB; i += BLK) g_fc[i] = 0u;
    if (tid == 0) {
        g_pos_cnt  = 0u;
        g_neg_cnt  = 0u;
        g_sum_main = 0.0;
        g_done     = 0u;
    }
}

// ---------------------------------------------------------------------------
extern "C" void kernel_launch(void* const* d_in, const int* in_sizes, int n_in,
                              void* d_out, int out_size)
{
    const float* pred = (const float*)d_in[0];
    const float* gt   = (const float*)d_in[1];
    const float* mask = (const float*)d_in[2];
    float* out = (float*)d_out;
    const int n = in_sizes[0];

    const float4* pred4 = (const float4*)pred;
    const float4* gt4   = (const float4*)gt;
    const float4* mask4 = (const float4*)mask;

    int n4 = n >> 2;
    int grid = (n4 + BLK - 1) / BLK;
    if (grid > GRID_CAP) grid = GRID_CAP;
    if (grid < 1) grid = 1;

    int iters = (n4 + grid * BLK - 1) / (grid * BLK);
    long long cap = (long long)iters * BLK * 4 + 8;   // elements (mult of 8)
    int use_scr = ((long long)grid * cap <= (long long)SCR_ELT) ? 1 : 0;

    k1_scan<<<grid, BLK>>>(pred4, gt4, mask4, pred, gt, mask, n, (int)cap, use_scr);
    k2_sums<<<grid, BLK>>>(pred4, gt4, mask4, pred, gt, mask, n, (int)cap, use_scr, out);
}